// round 3
// baseline (speedup 1.0000x reference)
#include <cuda_runtime.h>

#define FULL 0xFFFFFFFFu

constexpr int B   = 2048;
constexpr int NA  = 60;     // atoms per graph
constexpr int DG  = 6;      // max degree / neighbor slots
constexpr int AF  = 37;     // atom features
constexpr int BF  = 6;      // bond features
constexpr int HID = 128;    // hidden
constexpr int NC  = 12;     // classes

// ---- scratch (allocation-free: __device__ globals) ----
__device__ float g_x1[B * NA * HID];
__device__ float g_x2[B * NA * HID];

// ---------------------------------------------------------------------------
// Graph conv. feat = concat(self + sum(valid nbrs), bonds.sum(d));
// out = relu(feat @ W[deg] + b[deg]); zero if deg >= DG.
// One warp per atom; each lane computes 4 of 128 output channels.
// USE_EXT: read from the external pointer (conv1) vs. g_x2 (conv2).
// Output always goes to g_x1.
// All __shfl_sync / __ballot_sync are in uniform control flow (nb[] hoist).
// ---------------------------------------------------------------------------
template <int INF, bool USE_EXT>
__global__ __launch_bounds__(256)
void conv_kernel(const float* __restrict__ Xext,
                 const float* __restrict__ bonds,
                 const int*   __restrict__ edges,
                 const float* __restrict__ W,
                 const float* __restrict__ bias) {
    constexpr int IN = INF + BF;
    __shared__ float sfeat[8][IN + 2];

    const float* __restrict__ X = USE_EXT ? Xext : (const float*)g_x2;

    int w    = threadIdx.x >> 5;
    int lane = threadIdx.x & 31;
    int a    = blockIdx.x * 8 + w;        // atom id (b*NA + n)
    int rowbase = (a / NA) * NA;

    // edges + degree; broadcast neighbor ids in UNIFORM control flow
    int e = -1;
    if (lane < DG) e = edges[a * DG + lane];
    unsigned ball = __ballot_sync(FULL, e >= 0);
    int deg = __popc(ball);
    int nb[DG];
    #pragma unroll
    for (int d = 0; d < DG; d++) nb[d] = __shfl_sync(FULL, e, d);

    // feature assembly: self + masked neighbor sum (no sync ops inside)
    const float* xr = X + a * INF;
    for (int i = lane; i < INF; i += 32) {
        float s = xr[i];
        #pragma unroll
        for (int d = 0; d < DG; d++)
            if (nb[d] >= 0) s += X[(rowbase + nb[d]) * INF + i];
        sfeat[w][i] = s;
    }
    // inline bonds.sum over the degree axis (6 features, lanes 0..5)
    if (lane < BF) {
        const float* bp = bonds + a * (DG * BF) + lane;
        sfeat[w][INF + lane] = bp[0] + bp[BF] + bp[2*BF] + bp[3*BF] + bp[4*BF] + bp[5*BF];
    }
    __syncwarp();

    int o = lane * 4;
    float4 acc = make_float4(0.f, 0.f, 0.f, 0.f);
    if (deg < DG) {
        acc = *reinterpret_cast<const float4*>(bias + deg * HID + o);
        const float* wb = W + deg * IN * HID + o;
        #pragma unroll 4
        for (int i = 0; i < IN; i++) {
            float f = sfeat[w][i];
            float4 w4 = *reinterpret_cast<const float4*>(wb + i * HID);
            acc.x = fmaf(f, w4.x, acc.x);
            acc.y = fmaf(f, w4.y, acc.y);
            acc.z = fmaf(f, w4.z, acc.z);
            acc.w = fmaf(f, w4.w, acc.w);
        }
        acc.x = fmaxf(acc.x, 0.f);  acc.y = fmaxf(acc.y, 0.f);
        acc.z = fmaxf(acc.z, 0.f);  acc.w = fmaxf(acc.w, 0.f);
    }
    *reinterpret_cast<float4*>(g_x1 + a * HID + o) = acc;
}

// ---------------------------------------------------------------------------
// Max-pool over self + valid neighbors, zeroed when deg==0. g_x1 -> g_x2.
// One warp per atom; 4 channels per lane. 128/32 exact -> uniform loops.
// ---------------------------------------------------------------------------
__global__ __launch_bounds__(256)
void pool_kernel(const int* __restrict__ edges) {
    int w    = threadIdx.x >> 5;
    int lane = threadIdx.x & 31;
    int a    = blockIdx.x * 8 + w;
    int rowbase = (a / NA) * NA;

    int e = (lane < DG) ? edges[a * DG + lane] : -1;
    unsigned ball = __ballot_sync(FULL, e >= 0);
    int nb[DG];
    #pragma unroll
    for (int d = 0; d < DG; d++) nb[d] = __shfl_sync(FULL, e, d);

    int o = lane * 4;
    float4 v = *reinterpret_cast<const float4*>(g_x1 + a * HID + o);
    #pragma unroll
    for (int d = 0; d < DG; d++) {
        if (nb[d] >= 0) {
            float4 u = *reinterpret_cast<const float4*>(g_x1 + (rowbase + nb[d]) * HID + o);
            v.x = fmaxf(v.x, u.x);  v.y = fmaxf(v.y, u.y);
            v.z = fmaxf(v.z, u.z);  v.w = fmaxf(v.w, u.w);
        }
    }
    if (ball == 0u) v = make_float4(0.f, 0.f, 0.f, 0.f);
    *reinterpret_cast<float4*>(g_x2 + a * HID + o) = v;
}

// ---------------------------------------------------------------------------
// Fused: pool2 (inline, over g_x1) + graph-output aggregation + FC + sigmoid.
// Block per graph: 8 warps split the 60 atoms; per atom compute
// tanh(concat(pooled, bondsum) @ Wo + bo) * mask, accumulate; cross-warp
// reduce; 12-wide FC + sigmoid.
// ---------------------------------------------------------------------------
__global__ __launch_bounds__(256)
void gout_fc_kernel(const int*   __restrict__ edges,
                    const float* __restrict__ bonds,
                    const float* __restrict__ Wo,
                    const float* __restrict__ bo,
                    const float* __restrict__ Wfc,
                    const float* __restrict__ bfc,
                    float* __restrict__ out) {
    constexpr int IN = HID + BF;   // 134
    __shared__ float sfeat[8][IN + 2];
    __shared__ float red[8][HID];
    __shared__ float sfp[HID];

    int w    = threadIdx.x >> 5;
    int lane = threadIdx.x & 31;
    int bb   = blockIdx.x;
    int rowbase = bb * NA;
    int o    = lane * 4;

    float4 bo4 = *reinterpret_cast<const float4*>(bo + o);
    float4 acc = make_float4(0.f, 0.f, 0.f, 0.f);

    for (int n = w; n < NA; n += 8) {           // per-warp loop, no block sync inside
        int a = rowbase + n;
        int e = (lane < DG) ? edges[a * DG + lane] : -1;
        unsigned ball = __ballot_sync(FULL, e >= 0);
        int nb[DG];
        #pragma unroll
        for (int d = 0; d < DG; d++) nb[d] = __shfl_sync(FULL, e, d);

        // inline pool over g_x1 (128/32 exact -> uniform trip count)
        for (int i = lane; i < HID; i += 32) {
            float v = g_x1[a * HID + i];
            #pragma unroll
            for (int d = 0; d < DG; d++)
                if (nb[d] >= 0) v = fmaxf(v, g_x1[(rowbase + nb[d]) * HID + i]);
            sfeat[w][i] = (ball != 0u) ? v : 0.f;
        }
        if (lane < BF) {
            const float* bp = bonds + a * (DG * BF) + lane;
            sfeat[w][HID + lane] = bp[0] + bp[BF] + bp[2*BF] + bp[3*BF] + bp[4*BF] + bp[5*BF];
        }
        __syncwarp();

        float4 v = bo4;
        #pragma unroll 4
        for (int i = 0; i < IN; i++) {
            float f = sfeat[w][i];
            float4 w4 = *reinterpret_cast<const float4*>(Wo + i * HID + o);
            v.x = fmaf(f, w4.x, v.x);
            v.y = fmaf(f, w4.y, v.y);
            v.z = fmaf(f, w4.z, v.z);
            v.w = fmaf(f, w4.w, v.w);
        }
        if (ball != 0u) {
            acc.x += tanhf(v.x);  acc.y += tanhf(v.y);
            acc.z += tanhf(v.z);  acc.w += tanhf(v.w);
        }
        __syncwarp();
    }

    red[w][o]     = acc.x;
    red[w][o + 1] = acc.y;
    red[w][o + 2] = acc.z;
    red[w][o + 3] = acc.w;
    __syncthreads();

    int tid = threadIdx.x;
    if (tid < HID) {
        float s = 0.f;
        #pragma unroll
        for (int ww = 0; ww < 8; ww++) s += red[ww][tid];
        sfp[tid] = s;
    }
    __syncthreads();

    if (tid < NC) {
        float v = bfc[tid];
        #pragma unroll 8
        for (int oo = 0; oo < HID; oo++) v = fmaf(sfp[oo], Wfc[oo * NC + tid], v);
        out[bb * NC + tid] = 1.0f / (1.0f + expf(-v));
    }
}

// ---------------------------------------------------------------------------
extern "C" void kernel_launch(void* const* d_in, const int* in_sizes, int n_in,
                              void* d_out, int out_size) {
    const float* atoms = (const float*)d_in[0];   // (B,NA,37)
    const float* bonds = (const float*)d_in[1];   // (B,NA,6,6)
    const int*   edges = (const int*)  d_in[2];   // (B,NA,6) int32, -1 pad
    const float* W1    = (const float*)d_in[3];   // (6,43,128)
    const float* b1    = (const float*)d_in[4];   // (6,128)
    const float* W2    = (const float*)d_in[5];   // (6,134,128)
    const float* b2    = (const float*)d_in[6];   // (6,128)
    const float* Wo    = (const float*)d_in[7];   // (134,128)
    const float* bo    = (const float*)d_in[8];   // (128,)
    const float* Wfc   = (const float*)d_in[9];   // (128,12)
    const float* bfc   = (const float*)d_in[10];  // (12,)
    float* out = (float*)d_out;                   // (B,12)

    int convBlocks = (B * NA) / 8;   // 15360

    // 1) conv1: atoms -> g_x1
    conv_kernel<AF, true><<<convBlocks, 256>>>(atoms, bonds, edges, W1, b1);
    // 2) pool1: g_x1 -> g_x2
    pool_kernel<<<convBlocks, 256>>>(edges);
    // 3) conv2: g_x2 -> g_x1
    conv_kernel<HID, false><<<convBlocks, 256>>>(nullptr, bonds, edges, W2, b2);
    // 4) pool2 (inline) + gout + fc + sigmoid: g_x1 -> out
    gout_fc_kernel<<<B, 256>>>(edges, bonds, Wo, bo, Wfc, bfc, out);
}

// round 4
// speedup vs baseline: 1.3774x; 1.3774x over previous
#include <cuda_runtime.h>

#define FULL 0xFFFFFFFFu

constexpr int B   = 2048;
constexpr int NA  = 60;     // atoms per graph
constexpr int DG  = 6;      // max degree / neighbor slots
constexpr int AF  = 37;     // atom features
constexpr int BF  = 6;      // bond features
constexpr int HID = 128;    // hidden
constexpr int NC  = 12;     // classes
constexpr int BN  = B * NA; // 122880 atoms total
constexpr int TM  = 64;     // atom tile per conv block
constexpr int NB  = 7;      // degree buckets 0..6
constexpr int SP  = 68;     // sfeat row stride (floats): 16B-aligned, 4-way STS conflict

// ---- scratch (allocation-free: __device__ globals) ----
__device__ float g_x1[BN * HID];
__device__ float g_x2[BN * HID];
__device__ int   g_bidx[NB * BN];   // bucketed atom ids
__device__ int   g_bcnt[8];         // per-degree counts

// ---------------------------------------------------------------------------
__global__ void zero_cnt_kernel() {
    if (threadIdx.x < 8) g_bcnt[threadIdx.x] = 0;
}

// Bucket atoms by degree. Order within a bucket is nondeterministic but the
// downstream per-atom results are order-independent.
__global__ __launch_bounds__(256)
void prep_kernel(const int* __restrict__ edges) {
    int a = blockIdx.x * blockDim.x + threadIdx.x;
    if (a >= BN) return;
    int deg = 0;
    #pragma unroll
    for (int d = 0; d < DG; d++) deg += (edges[a * DG + d] >= 0);
    int pos = atomicAdd(&g_bcnt[deg], 1);
    g_bidx[deg * BN + pos] = a;
}

// ---------------------------------------------------------------------------
// Tiled graph conv over one degree bucket. Block = (deg, 64-atom tile).
// Stage feat = concat(self + nbr-sum, bondsum) for 64 atoms into shared
// (k-major), then GEMM: 256 threads as 32 channel-groups x 8 atom-groups,
// each thread = 4 channels x 8 atoms register tile. Output -> g_x1.
// ---------------------------------------------------------------------------
template <int INF, bool USE_EXT>
__global__ __launch_bounds__(256)
void conv_tiled_kernel(const float* __restrict__ Xext,
                       const float* __restrict__ bonds,
                       const int*   __restrict__ edges,
                       const float* __restrict__ W,
                       const float* __restrict__ bias) {
    constexpr int IN = INF + BF;
    __shared__ float sfeat[IN][SP];
    __shared__ int   satom[TM];

    const float* __restrict__ X = USE_EXT ? Xext : (const float*)g_x2;

    int deg = blockIdx.y;
    int cnt = g_bcnt[deg];
    int t0  = blockIdx.x * TM;
    if (t0 >= cnt) return;

    int tid  = threadIdx.x;
    int w    = tid >> 5;
    int lane = tid & 31;

    if (tid < TM) {
        int i = t0 + tid;
        satom[tid] = (i < cnt) ? g_bidx[deg * BN + i] : -1;
    }
    __syncthreads();

    // ---- stage features: 8 warps x 8 atoms each ----
    for (int al = w; al < TM; al += 8) {
        int a  = satom[al];
        int aa = (a >= 0) ? a : 0;
        int e  = -1;
        if (lane < DG && a >= 0) e = edges[aa * DG + lane];
        int nb[DG];
        #pragma unroll
        for (int d = 0; d < DG; d++) nb[d] = __shfl_sync(FULL, e, d);
        int rowbase = (aa / NA) * NA;

        const float* xr = X + aa * INF;
        for (int i = lane; i < INF; i += 32) {         // no sync ops inside
            float s = xr[i];
            #pragma unroll
            for (int d = 0; d < DG; d++)
                if (nb[d] >= 0) s += X[(rowbase + nb[d]) * INF + i];
            sfeat[i][al] = (a >= 0) ? s : 0.f;
        }
        if (lane < BF) {
            const float* bp = bonds + aa * (DG * BF) + lane;
            float s = bp[0] + bp[BF] + bp[2*BF] + bp[3*BF] + bp[4*BF] + bp[5*BF];
            sfeat[INF + lane][al] = (a >= 0) ? s : 0.f;
        }
    }
    __syncthreads();

    // ---- GEMM: thread = channels cg*4..+3, atoms ag*8..+7 ----
    int cg = tid >> 3;   // 0..31
    int ag = tid & 7;    // 0..7

    float4 acc[8];
    if (deg < DG) {
        float4 b4 = *reinterpret_cast<const float4*>(bias + deg * HID + cg * 4);
        #pragma unroll
        for (int j = 0; j < 8; j++) acc[j] = b4;

        const float* wb = W + deg * IN * HID + cg * 4;
        #pragma unroll 2
        for (int k = 0; k < IN; k++) {
            float4 w4 = *reinterpret_cast<const float4*>(wb + k * HID);
            const float* fr = &sfeat[k][ag * 8];
            float4 f0 = *reinterpret_cast<const float4*>(fr);
            float4 f1 = *reinterpret_cast<const float4*>(fr + 4);
            float fv[8] = {f0.x, f0.y, f0.z, f0.w, f1.x, f1.y, f1.z, f1.w};
            #pragma unroll
            for (int j = 0; j < 8; j++) {
                acc[j].x = fmaf(fv[j], w4.x, acc[j].x);
                acc[j].y = fmaf(fv[j], w4.y, acc[j].y);
                acc[j].z = fmaf(fv[j], w4.z, acc[j].z);
                acc[j].w = fmaf(fv[j], w4.w, acc[j].w);
            }
        }
        #pragma unroll
        for (int j = 0; j < 8; j++) {
            acc[j].x = fmaxf(acc[j].x, 0.f);  acc[j].y = fmaxf(acc[j].y, 0.f);
            acc[j].z = fmaxf(acc[j].z, 0.f);  acc[j].w = fmaxf(acc[j].w, 0.f);
        }
    } else {
        #pragma unroll
        for (int j = 0; j < 8; j++) acc[j] = make_float4(0.f, 0.f, 0.f, 0.f);
    }

    #pragma unroll
    for (int j = 0; j < 8; j++) {
        int a = satom[ag * 8 + j];
        if (a >= 0)
            *reinterpret_cast<float4*>(g_x1 + a * HID + cg * 4) = acc[j];
    }
}

// ---------------------------------------------------------------------------
// Max-pool over self + valid neighbors, zeroed when deg==0. g_x1 -> g_x2.
// ---------------------------------------------------------------------------
__global__ __launch_bounds__(256)
void pool_kernel(const int* __restrict__ edges) {
    int w    = threadIdx.x >> 5;
    int lane = threadIdx.x & 31;
    int a    = blockIdx.x * 8 + w;
    int rowbase = (a / NA) * NA;

    int e = (lane < DG) ? edges[a * DG + lane] : -1;
    unsigned ball = __ballot_sync(FULL, e >= 0);
    int nb[DG];
    #pragma unroll
    for (int d = 0; d < DG; d++) nb[d] = __shfl_sync(FULL, e, d);

    int o = lane * 4;
    float4 v = *reinterpret_cast<const float4*>(g_x1 + a * HID + o);
    #pragma unroll
    for (int d = 0; d < DG; d++) {
        if (nb[d] >= 0) {
            float4 u = *reinterpret_cast<const float4*>(g_x1 + (rowbase + nb[d]) * HID + o);
            v.x = fmaxf(v.x, u.x);  v.y = fmaxf(v.y, u.y);
            v.z = fmaxf(v.z, u.z);  v.w = fmaxf(v.w, u.w);
        }
    }
    if (ball == 0u) v = make_float4(0.f, 0.f, 0.f, 0.f);
    *reinterpret_cast<float4*>(g_x2 + a * HID + o) = v;
}

// ---------------------------------------------------------------------------
// Fused: pool2 (inline over g_x1) + gout (tanh masked-sum) + FC + sigmoid.
// Block per graph. Stage all 60 pooled feats in shared, then a 64x128 tiled
// GEMM against Wo (loaded once per block), tanh+mask+reduce, 12-wide FC.
// ---------------------------------------------------------------------------
__global__ __launch_bounds__(256)
void gout_fc_kernel(const int*   __restrict__ edges,
                    const float* __restrict__ bonds,
                    const float* __restrict__ Wo,
                    const float* __restrict__ bo,
                    const float* __restrict__ Wfc,
                    const float* __restrict__ bfc,
                    float* __restrict__ out) {
    constexpr int IN = HID + BF;   // 134
    __shared__ float sfeat[IN][SP];
    __shared__ float svalid[TM];
    __shared__ float4 sred[32][8];
    __shared__ float sfp[HID];

    int tid  = threadIdx.x;
    int w    = tid >> 5;
    int lane = tid & 31;
    int bb   = blockIdx.x;
    int rowbase = bb * NA;

    // ---- stage: inline pool + bondsum + validity ----
    for (int al = w; al < TM; al += 8) {
        bool ok = (al < NA);
        int a = rowbase + (ok ? al : 0);
        int e = -1;
        if (lane < DG && ok) e = edges[a * DG + lane];
        unsigned ball = __ballot_sync(FULL, e >= 0);
        int nb[DG];
        #pragma unroll
        for (int d = 0; d < DG; d++) nb[d] = __shfl_sync(FULL, e, d);

        bool valid = ok && (ball != 0u);
        #pragma unroll
        for (int i = lane; i < HID; i += 32) {    // uniform 4 iterations
            float v = g_x1[a * HID + i];
            #pragma unroll
            for (int d = 0; d < DG; d++)
                if (nb[d] >= 0) v = fmaxf(v, g_x1[(rowbase + nb[d]) * HID + i]);
            sfeat[i][al] = valid ? v : 0.f;
        }
        if (lane < BF) {
            const float* bp = bonds + a * (DG * BF) + lane;
            float s = bp[0] + bp[BF] + bp[2*BF] + bp[3*BF] + bp[4*BF] + bp[5*BF];
            sfeat[HID + lane][al] = valid ? s : 0.f;
        }
        if (lane == 0) svalid[al] = valid ? 1.f : 0.f;
    }
    __syncthreads();

    // ---- GEMM against Wo ----
    int cg = tid >> 3;
    int ag = tid & 7;

    float4 bo4 = *reinterpret_cast<const float4*>(bo + cg * 4);
    float4 acc[8];
    #pragma unroll
    for (int j = 0; j < 8; j++) acc[j] = bo4;

    const float* wb = Wo + cg * 4;
    #pragma unroll 2
    for (int k = 0; k < IN; k++) {
        float4 w4 = *reinterpret_cast<const float4*>(wb + k * HID);
        const float* fr = &sfeat[k][ag * 8];
        float4 f0 = *reinterpret_cast<const float4*>(fr);
        float4 f1 = *reinterpret_cast<const float4*>(fr + 4);
        float fv[8] = {f0.x, f0.y, f0.z, f0.w, f1.x, f1.y, f1.z, f1.w};
        #pragma unroll
        for (int j = 0; j < 8; j++) {
            acc[j].x = fmaf(fv[j], w4.x, acc[j].x);
            acc[j].y = fmaf(fv[j], w4.y, acc[j].y);
            acc[j].z = fmaf(fv[j], w4.z, acc[j].z);
            acc[j].w = fmaf(fv[j], w4.w, acc[j].w);
        }
    }

    // ---- tanh + mask + per-thread atom reduction ----
    float4 part = make_float4(0.f, 0.f, 0.f, 0.f);
    #pragma unroll
    for (int j = 0; j < 8; j++) {
        float vl = svalid[ag * 8 + j];
        part.x += vl * tanhf(acc[j].x);
        part.y += vl * tanhf(acc[j].y);
        part.z += vl * tanhf(acc[j].z);
        part.w += vl * tanhf(acc[j].w);
    }
    sred[cg][ag] = part;
    __syncthreads();

    // ---- cross-ag reduce to fp[128] ----
    if (tid < 32) {
        float4 s = sred[tid][0];
        #pragma unroll
        for (int g = 1; g < 8; g++) {
            float4 t = sred[tid][g];
            s.x += t.x;  s.y += t.y;  s.z += t.z;  s.w += t.w;
        }
        *reinterpret_cast<float4*>(sfp + tid * 4) = s;
    }
    __syncthreads();

    // ---- FC + sigmoid ----
    if (tid < NC) {
        float v = bfc[tid];
        #pragma unroll 8
        for (int o = 0; o < HID; o++) v = fmaf(sfp[o], Wfc[o * NC + tid], v);
        out[bb * NC + tid] = 1.0f / (1.0f + expf(-v));
    }
}

// ---------------------------------------------------------------------------
extern "C" void kernel_launch(void* const* d_in, const int* in_sizes, int n_in,
                              void* d_out, int out_size) {
    const float* atoms = (const float*)d_in[0];   // (B,NA,37)
    const float* bonds = (const float*)d_in[1];   // (B,NA,6,6)
    const int*   edges = (const int*)  d_in[2];   // (B,NA,6) int32, -1 pad
    const float* W1    = (const float*)d_in[3];   // (6,43,128)
    const float* b1    = (const float*)d_in[4];   // (6,128)
    const float* W2    = (const float*)d_in[5];   // (6,134,128)
    const float* b2    = (const float*)d_in[6];   // (6,128)
    const float* Wo    = (const float*)d_in[7];   // (134,128)
    const float* bo    = (const float*)d_in[8];   // (128,)
    const float* Wfc   = (const float*)d_in[9];   // (128,12)
    const float* bfc   = (const float*)d_in[10];  // (12,)
    float* out = (float*)d_out;                   // (B,12)

    // 0) bucket atoms by degree
    zero_cnt_kernel<<<1, 32>>>();
    prep_kernel<<<BN / 256, 256>>>(edges);

    dim3 convGrid(BN / TM, NB);   // (1920, 7); empty buckets exit immediately

    // 1) conv1: atoms -> g_x1
    conv_tiled_kernel<AF, true><<<convGrid, 256>>>(atoms, bonds, edges, W1, b1);
    // 2) pool1: g_x1 -> g_x2
    pool_kernel<<<BN / 8, 256>>>(edges);
    // 3) conv2: g_x2 -> g_x1
    conv_tiled_kernel<HID, false><<<convGrid, 256>>>(nullptr, bonds, edges, W2, b2);
    // 4) pool2 (inline) + gout + fc + sigmoid: g_x1 -> out
    gout_fc_kernel<<<B, 256>>>(edges, bonds, Wo, bo, Wfc, bfc, out);
}

// round 5
// speedup vs baseline: 1.4023x; 1.0181x over previous
#include <cuda_runtime.h>

#define FULL 0xFFFFFFFFu

constexpr int B   = 2048;
constexpr int NA  = 60;     // atoms per graph
constexpr int DG  = 6;      // max degree / neighbor slots
constexpr int AF  = 37;     // atom features
constexpr int BF  = 6;      // bond features
constexpr int HID = 128;    // hidden
constexpr int NC  = 12;     // classes
constexpr int BN  = B * NA; // 122880 atoms total
constexpr int TM  = 64;     // atom tile per conv block
constexpr int NB  = 7;      // degree buckets 0..6
constexpr int SP  = 68;     // sfeat row stride (floats); k*SP*4 = 272B (16B aligned)

// ---- scratch (allocation-free: __device__ globals) ----
__device__ float g_x1[BN * HID];
__device__ float g_x2[BN * HID];
__device__ int   g_bidx[NB * BN];   // bucketed atom ids
__device__ int   g_bcnt[8];         // per-degree counts

// ---- packed f32x2 helpers (sm_103a FFMA2 — ptxas never auto-fuses) ----
__device__ __forceinline__ unsigned long long pack2(float lo, float hi) {
    unsigned long long r;
    asm("mov.b64 %0, {%1, %2};" : "=l"(r) : "f"(lo), "f"(hi));
    return r;
}
__device__ __forceinline__ void fma2(unsigned long long& d,
                                     unsigned long long a, unsigned long long b) {
    asm("fma.rn.f32x2 %0, %1, %2, %0;" : "+l"(d) : "l"(a), "l"(b));
}
__device__ __forceinline__ float2 unpack2(unsigned long long v) {
    float lo, hi;
    asm("mov.b64 {%0, %1}, %2;" : "=f"(lo), "=f"(hi) : "l"(v));
    return make_float2(lo, hi);
}
__device__ __forceinline__ float htanh(float x) {
    float y;
    asm("tanh.approx.f32 %0, %1;" : "=f"(y) : "f"(x));
    return y;
}

// ---------------------------------------------------------------------------
__global__ void zero_cnt_kernel() {
    if (threadIdx.x < 8) g_bcnt[threadIdx.x] = 0;
}

// Bucket atoms by degree (order within bucket irrelevant: per-atom outputs).
__global__ __launch_bounds__(256)
void prep_kernel(const int* __restrict__ edges) {
    int a = blockIdx.x * blockDim.x + threadIdx.x;
    if (a >= BN) return;
    int deg = 0;
    #pragma unroll
    for (int d = 0; d < DG; d++) deg += (edges[a * DG + d] >= 0);
    int pos = atomicAdd(&g_bcnt[deg], 1);
    g_bidx[deg * BN + pos] = a;
}

// ---------------------------------------------------------------------------
// Tiled graph conv over one degree bucket. Block = (deg, 64-atom tile).
// Stage feat (k-major) in shared, then packed-GEMM: thread = 4 ch x 4
// atom-pairs (8 atoms), 16 fma.rn.f32x2 per k-step. Output -> g_x1.
// ---------------------------------------------------------------------------
template <int INF, bool USE_EXT>
__global__ __launch_bounds__(256)
void conv_tiled_kernel(const float* __restrict__ Xext,
                       const float* __restrict__ bonds,
                       const int*   __restrict__ edges,
                       const float* __restrict__ W,
                       const float* __restrict__ bias) {
    constexpr int IN = INF + BF;
    __shared__ __align__(16) float sfeat[IN][SP];
    __shared__ int satom[TM];

    const float* __restrict__ X = USE_EXT ? Xext : (const float*)g_x2;

    int deg = blockIdx.y;
    int cnt = g_bcnt[deg];
    int t0  = blockIdx.x * TM;
    if (t0 >= cnt) return;

    int tid  = threadIdx.x;
    int w    = tid >> 5;
    int lane = tid & 31;

    if (tid < TM) {
        int i = t0 + tid;
        satom[tid] = (i < cnt) ? g_bidx[deg * BN + i] : -1;
    }
    __syncthreads();

    // ---- stage features: 8 warps x 8 atoms each ----
    for (int al = w; al < TM; al += 8) {
        int a  = satom[al];
        int aa = (a >= 0) ? a : 0;
        int e  = -1;
        if (lane < DG && a >= 0) e = edges[aa * DG + lane];
        int nb[DG];
        #pragma unroll
        for (int d = 0; d < DG; d++) nb[d] = __shfl_sync(FULL, e, d);
        int rowbase = (aa / NA) * NA;

        const float* xr = X + aa * INF;
        for (int i = lane; i < INF; i += 32) {       // no sync ops inside
            float s = xr[i];
            #pragma unroll
            for (int d = 0; d < DG; d++)
                if (nb[d] >= 0) s += X[(rowbase + nb[d]) * INF + i];
            sfeat[i][al] = (a >= 0) ? s : 0.f;
        }
        if (lane < BF) {
            const float* bp = bonds + aa * (DG * BF) + lane;
            float s = bp[0] + bp[BF] + bp[2*BF] + bp[3*BF] + bp[4*BF] + bp[5*BF];
            sfeat[INF + lane][al] = (a >= 0) ? s : 0.f;
        }
    }
    __syncthreads();

    // ---- packed GEMM: thread = ch cg*4..+3 x atoms ag*8..+7 (4 pairs) ----
    int cg = tid >> 3;   // 0..31
    int ag = tid & 7;    // 0..7

    unsigned long long acc2[4][4];   // [channel][atom-pair]
    if (deg < DG) {
        float4 b4 = *reinterpret_cast<const float4*>(bias + deg * HID + cg * 4);
        {
            unsigned long long bx = pack2(b4.x, b4.x), by = pack2(b4.y, b4.y);
            unsigned long long bz = pack2(b4.z, b4.z), bw = pack2(b4.w, b4.w);
            #pragma unroll
            for (int p = 0; p < 4; p++) {
                acc2[0][p] = bx;  acc2[1][p] = by;
                acc2[2][p] = bz;  acc2[3][p] = bw;
            }
        }

        const float* wb = W + deg * IN * HID + cg * 4;
        #pragma unroll 2
        for (int k = 0; k < IN; k++) {
            float4 w4 = *reinterpret_cast<const float4*>(wb + k * HID);
            unsigned long long wp[4] = {pack2(w4.x, w4.x), pack2(w4.y, w4.y),
                                        pack2(w4.z, w4.z), pack2(w4.w, w4.w)};
            const ulonglong2* fr = reinterpret_cast<const ulonglong2*>(&sfeat[k][ag * 8]);
            ulonglong2 fA = fr[0], fB = fr[1];
            unsigned long long fp_[4] = {fA.x, fA.y, fB.x, fB.y};
            #pragma unroll
            for (int c = 0; c < 4; c++)
                #pragma unroll
                for (int p = 0; p < 4; p++)
                    fma2(acc2[c][p], fp_[p], wp[c]);
        }

        #pragma unroll
        for (int p = 0; p < 4; p++) {
            float2 c0 = unpack2(acc2[0][p]), c1 = unpack2(acc2[1][p]);
            float2 c2 = unpack2(acc2[2][p]), c3 = unpack2(acc2[3][p]);
            int a0 = satom[ag * 8 + 2 * p];
            int a1 = satom[ag * 8 + 2 * p + 1];
            if (a0 >= 0) {
                float4 o4 = make_float4(fmaxf(c0.x, 0.f), fmaxf(c1.x, 0.f),
                                        fmaxf(c2.x, 0.f), fmaxf(c3.x, 0.f));
                *reinterpret_cast<float4*>(g_x1 + a0 * HID + cg * 4) = o4;
            }
            if (a1 >= 0) {
                float4 o4 = make_float4(fmaxf(c0.y, 0.f), fmaxf(c1.y, 0.f),
                                        fmaxf(c2.y, 0.f), fmaxf(c3.y, 0.f));
                *reinterpret_cast<float4*>(g_x1 + a1 * HID + cg * 4) = o4;
            }
        }
    } else {
        float4 z = make_float4(0.f, 0.f, 0.f, 0.f);
        #pragma unroll
        for (int j = 0; j < 8; j++) {
            int a = satom[ag * 8 + j];
            if (a >= 0)
                *reinterpret_cast<float4*>(g_x1 + a * HID + cg * 4) = z;
        }
    }
}

// ---------------------------------------------------------------------------
// Max-pool over self + valid neighbors, zeroed when deg==0. g_x1 -> g_x2.
// ---------------------------------------------------------------------------
__global__ __launch_bounds__(256)
void pool_kernel(const int* __restrict__ edges) {
    int w    = threadIdx.x >> 5;
    int lane = threadIdx.x & 31;
    int a    = blockIdx.x * 8 + w;
    int rowbase = (a / NA) * NA;

    int e = (lane < DG) ? edges[a * DG + lane] : -1;
    unsigned ball = __ballot_sync(FULL, e >= 0);
    int nb[DG];
    #pragma unroll
    for (int d = 0; d < DG; d++) nb[d] = __shfl_sync(FULL, e, d);

    int o = lane * 4;
    float4 v = *reinterpret_cast<const float4*>(g_x1 + a * HID + o);
    #pragma unroll
    for (int d = 0; d < DG; d++) {
        if (nb[d] >= 0) {
            float4 u = *reinterpret_cast<const float4*>(g_x1 + (rowbase + nb[d]) * HID + o);
            v.x = fmaxf(v.x, u.x);  v.y = fmaxf(v.y, u.y);
            v.z = fmaxf(v.z, u.z);  v.w = fmaxf(v.w, u.w);
        }
    }
    if (ball == 0u) v = make_float4(0.f, 0.f, 0.f, 0.f);
    *reinterpret_cast<float4*>(g_x2 + a * HID + o) = v;
}

// ---------------------------------------------------------------------------
// Fused: pool2 (inline over g_x1) + gout (tanh masked-sum) + FC + sigmoid.
// Same packed-GEMM layout; tanh via HW tanh.approx.
// ---------------------------------------------------------------------------
__global__ __launch_bounds__(256)
void gout_fc_kernel(const int*   __restrict__ edges,
                    const float* __restrict__ bonds,
                    const float* __restrict__ Wo,
                    const float* __restrict__ bo,
                    const float* __restrict__ Wfc,
                    const float* __restrict__ bfc,
                    float* __restrict__ out) {
    constexpr int IN = HID + BF;   // 134
    __shared__ __align__(16) float sfeat[IN][SP];
    __shared__ float svalid[TM];
    __shared__ float4 sred[32][8];
    __shared__ float sfp[HID];

    int tid  = threadIdx.x;
    int w    = tid >> 5;
    int lane = tid & 31;
    int bb   = blockIdx.x;
    int rowbase = bb * NA;

    // ---- stage: inline pool + bondsum + validity ----
    for (int al = w; al < TM; al += 8) {
        bool ok = (al < NA);
        int a = rowbase + (ok ? al : 0);
        int e = -1;
        if (lane < DG && ok) e = edges[a * DG + lane];
        unsigned ball = __ballot_sync(FULL, e >= 0);
        int nb[DG];
        #pragma unroll
        for (int d = 0; d < DG; d++) nb[d] = __shfl_sync(FULL, e, d);

        bool valid = ok && (ball != 0u);
        #pragma unroll
        for (int i = lane; i < HID; i += 32) {    // uniform 4 iterations
            float v = g_x1[a * HID + i];
            #pragma unroll
            for (int d = 0; d < DG; d++)
                if (nb[d] >= 0) v = fmaxf(v, g_x1[(rowbase + nb[d]) * HID + i]);
            sfeat[i][al] = valid ? v : 0.f;
        }
        if (lane < BF) {
            const float* bp = bonds + a * (DG * BF) + lane;
            float s = bp[0] + bp[BF] + bp[2*BF] + bp[3*BF] + bp[4*BF] + bp[5*BF];
            sfeat[HID + lane][al] = valid ? s : 0.f;
        }
        if (lane == 0) svalid[al] = valid ? 1.f : 0.f;
    }
    __syncthreads();

    // ---- packed GEMM against Wo ----
    int cg = tid >> 3;
    int ag = tid & 7;

    unsigned long long acc2[4][4];
    {
        float4 b4 = *reinterpret_cast<const float4*>(bo + cg * 4);
        unsigned long long bx = pack2(b4.x, b4.x), by = pack2(b4.y, b4.y);
        unsigned long long bz = pack2(b4.z, b4.z), bw = pack2(b4.w, b4.w);
        #pragma unroll
        for (int p = 0; p < 4; p++) {
            acc2[0][p] = bx;  acc2[1][p] = by;
            acc2[2][p] = bz;  acc2[3][p] = bw;
        }
    }

    const float* wb = Wo + cg * 4;
    #pragma unroll 2
    for (int k = 0; k < IN; k++) {
        float4 w4 = *reinterpret_cast<const float4*>(wb + k * HID);
        unsigned long long wp[4] = {pack2(w4.x, w4.x), pack2(w4.y, w4.y),
                                    pack2(w4.z, w4.z), pack2(w4.w, w4.w)};
        const ulonglong2* fr = reinterpret_cast<const ulonglong2*>(&sfeat[k][ag * 8]);
        ulonglong2 fA = fr[0], fB = fr[1];
        unsigned long long fp_[4] = {fA.x, fA.y, fB.x, fB.y};
        #pragma unroll
        for (int c = 0; c < 4; c++)
            #pragma unroll
            for (int p = 0; p < 4; p++)
                fma2(acc2[c][p], fp_[p], wp[c]);
    }

    // ---- tanh + mask + per-thread atom reduction ----
    float4 part = make_float4(0.f, 0.f, 0.f, 0.f);
    #pragma unroll
    for (int p = 0; p < 4; p++) {
        float2 c0 = unpack2(acc2[0][p]), c1 = unpack2(acc2[1][p]);
        float2 c2 = unpack2(acc2[2][p]), c3 = unpack2(acc2[3][p]);
        float v0 = svalid[ag * 8 + 2 * p];
        float v1 = svalid[ag * 8 + 2 * p + 1];
        part.x += v0 * htanh(c0.x) + v1 * htanh(c0.y);
        part.y += v0 * htanh(c1.x) + v1 * htanh(c1.y);
        part.z += v0 * htanh(c2.x) + v1 * htanh(c2.y);
        part.w += v0 * htanh(c3.x) + v1 * htanh(c3.y);
    }
    sred[cg][ag] = part;
    __syncthreads();

    // ---- cross-ag reduce to fp[128] ----
    if (tid < 32) {
        float4 s = sred[tid][0];
        #pragma unroll
        for (int g = 1; g < 8; g++) {
            float4 t = sred[tid][g];
            s.x += t.x;  s.y += t.y;  s.z += t.z;  s.w += t.w;
        }
        *reinterpret_cast<float4*>(sfp + tid * 4) = s;
    }
    __syncthreads();

    // ---- FC + sigmoid ----
    if (tid < NC) {
        float v = bfc[tid];
        #pragma unroll 8
        for (int o = 0; o < HID; o++) v = fmaf(sfp[o], Wfc[o * NC + tid], v);
        out[bb * NC + tid] = 1.0f / (1.0f + expf(-v));
    }
}

// ---------------------------------------------------------------------------
extern "C" void kernel_launch(void* const* d_in, const int* in_sizes, int n_in,
                              void* d_out, int out_size) {
    const float* atoms = (const float*)d_in[0];   // (B,NA,37)
    const float* bonds = (const float*)d_in[1];   // (B,NA,6,6)
    const int*   edges = (const int*)  d_in[2];   // (B,NA,6) int32, -1 pad
    const float* W1    = (const float*)d_in[3];   // (6,43,128)
    const float* b1    = (const float*)d_in[4];   // (6,128)
    const float* W2    = (const float*)d_in[5];   // (6,134,128)
    const float* b2    = (const float*)d_in[6];   // (6,128)
    const float* Wo    = (const float*)d_in[7];   // (134,128)
    const float* bo    = (const float*)d_in[8];   // (128,)
    const float* Wfc   = (const float*)d_in[9];   // (128,12)
    const float* bfc   = (const float*)d_in[10];  // (12,)
    float* out = (float*)d_out;                   // (B,12)

    // 0) bucket atoms by degree
    zero_cnt_kernel<<<1, 32>>>();
    prep_kernel<<<BN / 256, 256>>>(edges);

    dim3 convGrid(BN / TM, NB);   // (1920, 7); empty buckets exit immediately

    // 1) conv1: atoms -> g_x1
    conv_tiled_kernel<AF, true><<<convGrid, 256>>>(atoms, bonds, edges, W1, b1);
    // 2) pool1: g_x1 -> g_x2
    pool_kernel<<<BN / 8, 256>>>(edges);
    // 3) conv2: g_x2 -> g_x1
    conv_tiled_kernel<HID, false><<<convGrid, 256>>>(nullptr, bonds, edges, W2, b2);
    // 4) pool2 (inline) + gout + fc + sigmoid: g_x1 -> out
    gout_fc_kernel<<<B, 256>>>(edges, bonds, Wo, bo, Wfc, bfc, out);
}

// round 6
// speedup vs baseline: 1.4119x; 1.0068x over previous
#include <cuda_runtime.h>

#define FULL 0xFFFFFFFFu

constexpr int B   = 2048;
constexpr int NA  = 60;     // atoms per graph
constexpr int DG  = 6;      // max degree / neighbor slots
constexpr int AF  = 37;     // atom features
constexpr int BF  = 6;      // bond features
constexpr int HID = 128;    // hidden
constexpr int NC  = 12;     // classes
constexpr int BN  = B * NA; // 122880 atoms total
constexpr int TM  = 64;     // atom tile per conv block
constexpr int NB  = 7;      // degree buckets 0..6
constexpr int SP  = 68;     // sfeat row stride (floats); k*SP*4 = 272B (16B aligned)

// ---- scratch (allocation-free: __device__ globals) ----
__device__ float g_x1[BN * HID];
__device__ float g_x2[BN * HID];
__device__ int   g_bidx[NB * BN];   // bucketed atom ids
__device__ int   g_bcnt[8];         // per-degree counts

// ---- packed f32x2 helpers (sm_103a FFMA2 — ptxas never auto-fuses) ----
__device__ __forceinline__ unsigned long long pack2(float lo, float hi) {
    unsigned long long r;
    asm("mov.b64 %0, {%1, %2};" : "=l"(r) : "f"(lo), "f"(hi));
    return r;
}
__device__ __forceinline__ void fma2(unsigned long long& d,
                                     unsigned long long a, unsigned long long b) {
    asm("fma.rn.f32x2 %0, %1, %2, %0;" : "+l"(d) : "l"(a), "l"(b));
}
__device__ __forceinline__ float2 unpack2(unsigned long long v) {
    float lo, hi;
    asm("mov.b64 {%0, %1}, %2;" : "=f"(lo), "=f"(hi) : "l"(v));
    return make_float2(lo, hi);
}
__device__ __forceinline__ float htanh(float x) {
    float y;
    asm("tanh.approx.f32 %0, %1;" : "=f"(y) : "f"(x));
    return y;
}

// ---------------------------------------------------------------------------
__global__ void zero_cnt_kernel() {
    if (threadIdx.x < 8) g_bcnt[threadIdx.x] = 0;
}

// Bucket atoms by degree (order within bucket irrelevant: per-atom outputs).
__global__ __launch_bounds__(256)
void prep_kernel(const int* __restrict__ edges) {
    int a = blockIdx.x * blockDim.x + threadIdx.x;
    if (a >= BN) return;
    int deg = 0;
    #pragma unroll
    for (int d = 0; d < DG; d++) deg += (edges[a * DG + d] >= 0);
    int pos = atomicAdd(&g_bcnt[deg], 1);
    g_bidx[deg * BN + pos] = a;
}

// ---------------------------------------------------------------------------
// Tiled graph conv over one degree bucket. Block = (deg, 64-atom tile).
// Stage feat (k-major) in shared, then packed-GEMM: thread = 4 ch x 4
// atom-pairs (8 atoms), 16 fma.rn.f32x2 per k-step. Output -> g_x1.
// ---------------------------------------------------------------------------
template <int INF, bool USE_EXT>
__global__ __launch_bounds__(256)
void conv_tiled_kernel(const float* __restrict__ Xext,
                       const float* __restrict__ bonds,
                       const int*   __restrict__ edges,
                       const float* __restrict__ W,
                       const float* __restrict__ bias) {
    constexpr int IN = INF + BF;
    __shared__ __align__(16) float sfeat[IN][SP];
    __shared__ int satom[TM];

    const float* __restrict__ X = USE_EXT ? Xext : (const float*)g_x2;

    int deg = blockIdx.y;
    int cnt = g_bcnt[deg];
    int t0  = blockIdx.x * TM;
    if (t0 >= cnt) return;

    int tid  = threadIdx.x;
    int w    = tid >> 5;
    int lane = tid & 31;

    if (tid < TM) {
        int i = t0 + tid;
        satom[tid] = (i < cnt) ? g_bidx[deg * BN + i] : -1;
    }
    __syncthreads();

    // ---- stage features: 8 warps x 8 atoms each ----
    for (int al = w; al < TM; al += 8) {
        int a  = satom[al];
        int aa = (a >= 0) ? a : 0;
        int e  = -1;
        if (lane < DG && a >= 0) e = edges[aa * DG + lane];
        int nb[DG];
        #pragma unroll
        for (int d = 0; d < DG; d++) nb[d] = __shfl_sync(FULL, e, d);
        int rowbase = (aa / NA) * NA;

        const float* xr = X + aa * INF;
        for (int i = lane; i < INF; i += 32) {       // no sync ops inside
            float s = xr[i];
            #pragma unroll
            for (int d = 0; d < DG; d++)
                if (nb[d] >= 0) s += X[(rowbase + nb[d]) * INF + i];
            sfeat[i][al] = (a >= 0) ? s : 0.f;
        }
        if (lane < BF) {
            const float* bp = bonds + aa * (DG * BF) + lane;
            float s = bp[0] + bp[BF] + bp[2*BF] + bp[3*BF] + bp[4*BF] + bp[5*BF];
            sfeat[INF + lane][al] = (a >= 0) ? s : 0.f;
        }
    }
    __syncthreads();

    // ---- packed GEMM: thread = ch cg*4..+3 x atoms ag*8..+7 (4 pairs) ----
    int cg = tid >> 3;   // 0..31
    int ag = tid & 7;    // 0..7

    unsigned long long acc2[4][4];   // [channel][atom-pair]
    if (deg < DG) {
        float4 b4 = *reinterpret_cast<const float4*>(bias + deg * HID + cg * 4);
        {
            unsigned long long bx = pack2(b4.x, b4.x), by = pack2(b4.y, b4.y);
            unsigned long long bz = pack2(b4.z, b4.z), bw = pack2(b4.w, b4.w);
            #pragma unroll
            for (int p = 0; p < 4; p++) {
                acc2[0][p] = bx;  acc2[1][p] = by;
                acc2[2][p] = bz;  acc2[3][p] = bw;
            }
        }

        const float* wb = W + deg * IN * HID + cg * 4;
        #pragma unroll 2
        for (int k = 0; k < IN; k++) {
            float4 w4 = *reinterpret_cast<const float4*>(wb + k * HID);
            unsigned long long wp[4] = {pack2(w4.x, w4.x), pack2(w4.y, w4.y),
                                        pack2(w4.z, w4.z), pack2(w4.w, w4.w)};
            const ulonglong2* fr = reinterpret_cast<const ulonglong2*>(&sfeat[k][ag * 8]);
            ulonglong2 fA = fr[0], fB = fr[1];
            unsigned long long fp_[4] = {fA.x, fA.y, fB.x, fB.y};
            #pragma unroll
            for (int c = 0; c < 4; c++)
                #pragma unroll
                for (int p = 0; p < 4; p++)
                    fma2(acc2[c][p], fp_[p], wp[c]);
        }

        #pragma unroll
        for (int p = 0; p < 4; p++) {
            float2 c0 = unpack2(acc2[0][p]), c1 = unpack2(acc2[1][p]);
            float2 c2 = unpack2(acc2[2][p]), c3 = unpack2(acc2[3][p]);
            int a0 = satom[ag * 8 + 2 * p];
            int a1 = satom[ag * 8 + 2 * p + 1];
            if (a0 >= 0) {
                float4 o4 = make_float4(fmaxf(c0.x, 0.f), fmaxf(c1.x, 0.f),
                                        fmaxf(c2.x, 0.f), fmaxf(c3.x, 0.f));
                *reinterpret_cast<float4*>(g_x1 + a0 * HID + cg * 4) = o4;
            }
            if (a1 >= 0) {
                float4 o4 = make_float4(fmaxf(c0.y, 0.f), fmaxf(c1.y, 0.f),
                                        fmaxf(c2.y, 0.f), fmaxf(c3.y, 0.f));
                *reinterpret_cast<float4*>(g_x1 + a1 * HID + cg * 4) = o4;
            }
        }
    } else {
        float4 z = make_float4(0.f, 0.f, 0.f, 0.f);
        #pragma unroll
        for (int j = 0; j < 8; j++) {
            int a = satom[ag * 8 + j];
            if (a >= 0)
                *reinterpret_cast<float4*>(g_x1 + a * HID + cg * 4) = z;
        }
    }
}

// ---------------------------------------------------------------------------
// Max-pool over self + valid neighbors, zeroed when deg==0. g_x1 -> g_x2.
// ---------------------------------------------------------------------------
__global__ __launch_bounds__(256)
void pool_kernel(const int* __restrict__ edges) {
    int w    = threadIdx.x >> 5;
    int lane = threadIdx.x & 31;
    int a    = blockIdx.x * 8 + w;
    int rowbase = (a / NA) * NA;

    int e = (lane < DG) ? edges[a * DG + lane] : -1;
    unsigned ball = __ballot_sync(FULL, e >= 0);
    int nb[DG];
    #pragma unroll
    for (int d = 0; d < DG; d++) nb[d] = __shfl_sync(FULL, e, d);

    int o = lane * 4;
    float4 v = *reinterpret_cast<const float4*>(g_x1 + a * HID + o);
    #pragma unroll
    for (int d = 0; d < DG; d++) {
        if (nb[d] >= 0) {
            float4 u = *reinterpret_cast<const float4*>(g_x1 + (rowbase + nb[d]) * HID + o);
            v.x = fmaxf(v.x, u.x);  v.y = fmaxf(v.y, u.y);
            v.z = fmaxf(v.z, u.z);  v.w = fmaxf(v.w, u.w);
        }
    }
    if (ball == 0u) v = make_float4(0.f, 0.f, 0.f, 0.f);
    *reinterpret_cast<float4*>(g_x2 + a * HID + o) = v;
}

// ---------------------------------------------------------------------------
// Fused: pool2 (inline over g_x1) + gout (tanh masked-sum) + FC + sigmoid.
// Same packed-GEMM layout; tanh via HW tanh.approx.
// ---------------------------------------------------------------------------
__global__ __launch_bounds__(256)
void gout_fc_kernel(const int*   __restrict__ edges,
                    const float* __restrict__ bonds,
                    const float* __restrict__ Wo,
                    const float* __restrict__ bo,
                    const float* __restrict__ Wfc,
                    const float* __restrict__ bfc,
                    float* __restrict__ out) {
    constexpr int IN = HID + BF;   // 134
    __shared__ __align__(16) float sfeat[IN][SP];
    __shared__ float svalid[TM];
    __shared__ float4 sred[32][8];
    __shared__ float sfp[HID];

    int tid  = threadIdx.x;
    int w    = tid >> 5;
    int lane = tid & 31;
    int bb   = blockIdx.x;
    int rowbase = bb * NA;

    // ---- stage: inline pool + bondsum + validity ----
    for (int al = w; al < TM; al += 8) {
        bool ok = (al < NA);
        int a = rowbase + (ok ? al : 0);
        int e = -1;
        if (lane < DG && ok) e = edges[a * DG + lane];
        unsigned ball = __ballot_sync(FULL, e >= 0);
        int nb[DG];
        #pragma unroll
        for (int d = 0; d < DG; d++) nb[d] = __shfl_sync(FULL, e, d);

        bool valid = ok && (ball != 0u);
        #pragma unroll
        for (int i = lane; i < HID; i += 32) {    // uniform 4 iterations
            float v = g_x1[a * HID + i];
            #pragma unroll
            for (int d = 0; d < DG; d++)
                if (nb[d] >= 0) v = fmaxf(v, g_x1[(rowbase + nb[d]) * HID + i]);
            sfeat[i][al] = valid ? v : 0.f;
        }
        if (lane < BF) {
            const float* bp = bonds + a * (DG * BF) + lane;
            float s = bp[0] + bp[BF] + bp[2*BF] + bp[3*BF] + bp[4*BF] + bp[5*BF];
            sfeat[HID + lane][al] = valid ? s : 0.f;
        }
        if (lane == 0) svalid[al] = valid ? 1.f : 0.f;
    }
    __syncthreads();

    // ---- packed GEMM against Wo ----
    int cg = tid >> 3;
    int ag = tid & 7;

    unsigned long long acc2[4][4];
    {
        float4 b4 = *reinterpret_cast<const float4*>(bo + cg * 4);
        unsigned long long bx = pack2(b4.x, b4.x), by = pack2(b4.y, b4.y);
        unsigned long long bz = pack2(b4.z, b4.z), bw = pack2(b4.w, b4.w);
        #pragma unroll
        for (int p = 0; p < 4; p++) {
            acc2[0][p] = bx;  acc2[1][p] = by;
            acc2[2][p] = bz;  acc2[3][p] = bw;
        }
    }

    const float* wb = Wo + cg * 4;
    #pragma unroll 2
    for (int k = 0; k < IN; k++) {
        float4 w4 = *reinterpret_cast<const float4*>(wb + k * HID);
        unsigned long long wp[4] = {pack2(w4.x, w4.x), pack2(w4.y, w4.y),
                                    pack2(w4.z, w4.z), pack2(w4.w, w4.w)};
        const ulonglong2* fr = reinterpret_cast<const ulonglong2*>(&sfeat[k][ag * 8]);
        ulonglong2 fA = fr[0], fB = fr[1];
        unsigned long long fp_[4] = {fA.x, fA.y, fB.x, fB.y};
        #pragma unroll
        for (int c = 0; c < 4; c++)
            #pragma unroll
            for (int p = 0; p < 4; p++)
                fma2(acc2[c][p], fp_[p], wp[c]);
    }

    // ---- tanh + mask + per-thread atom reduction ----
    float4 part = make_float4(0.f, 0.f, 0.f, 0.f);
    #pragma unroll
    for (int p = 0; p < 4; p++) {
        float2 c0 = unpack2(acc2[0][p]), c1 = unpack2(acc2[1][p]);
        float2 c2 = unpack2(acc2[2][p]), c3 = unpack2(acc2[3][p]);
        float v0 = svalid[ag * 8 + 2 * p];
        float v1 = svalid[ag * 8 + 2 * p + 1];
        part.x += v0 * htanh(c0.x) + v1 * htanh(c0.y);
        part.y += v0 * htanh(c1.x) + v1 * htanh(c1.y);
        part.z += v0 * htanh(c2.x) + v1 * htanh(c2.y);
        part.w += v0 * htanh(c3.x) + v1 * htanh(c3.y);
    }
    sred[cg][ag] = part;
    __syncthreads();

    // ---- cross-ag reduce to fp[128] ----
    if (tid < 32) {
        float4 s = sred[tid][0];
        #pragma unroll
        for (int g = 1; g < 8; g++) {
            float4 t = sred[tid][g];
            s.x += t.x;  s.y += t.y;  s.z += t.z;  s.w += t.w;
        }
        *reinterpret_cast<float4*>(sfp + tid * 4) = s;
    }
    __syncthreads();

    // ---- FC + sigmoid ----
    if (tid < NC) {
        float v = bfc[tid];
        #pragma unroll 8
        for (int o = 0; o < HID; o++) v = fmaf(sfp[o], Wfc[o * NC + tid], v);
        out[bb * NC + tid] = 1.0f / (1.0f + expf(-v));
    }
}

// ---------------------------------------------------------------------------
extern "C" void kernel_launch(void* const* d_in, const int* in_sizes, int n_in,
                              void* d_out, int out_size) {
    const float* atoms = (const float*)d_in[0];   // (B,NA,37)
    const float* bonds = (const float*)d_in[1];   // (B,NA,6,6)
    const int*   edges = (const int*)  d_in[2];   // (B,NA,6) int32, -1 pad
    const float* W1    = (const float*)d_in[3];   // (6,43,128)
    const float* b1    = (const float*)d_in[4];   // (6,128)
    const float* W2    = (const float*)d_in[5];   // (6,134,128)
    const float* b2    = (const float*)d_in[6];   // (6,128)
    const float* Wo    = (const float*)d_in[7];   // (134,128)
    const float* bo    = (const float*)d_in[8];   // (128,)
    const float* Wfc   = (const float*)d_in[9];   // (128,12)
    const float* bfc   = (const float*)d_in[10];  // (12,)
    float* out = (float*)d_out;                   // (B,12)

    // 0) bucket atoms by degree
    zero_cnt_kernel<<<1, 32>>>();
    prep_kernel<<<BN / 256, 256>>>(edges);

    dim3 convGrid(BN / TM, NB);   // (1920, 7); empty buckets exit immediately

    // 1) conv1: atoms -> g_x1
    conv_tiled_kernel<AF, true><<<convGrid, 256>>>(atoms, bonds, edges, W1, b1);
    // 2) pool1: g_x1 -> g_x2
    pool_kernel<<<BN / 8, 256>>>(edges);
    // 3) conv2: g_x2 -> g_x1
    conv_tiled_kernel<HID, false><<<convGrid, 256>>>(nullptr, bonds, edges, W2, b2);
    // 4) pool2 (inline) + gout + fc + sigmoid: g_x1 -> out
    gout_fc_kernel<<<B, 256>>>(edges, bonds, Wo, bo, Wfc, bfc, out);
}

// round 8
// speedup vs baseline: 1.9676x; 1.3936x over previous
#include <cuda_runtime.h>
#include <cuda_bf16.h>
#include <cstdint>

#define FULL 0xFFFFFFFFu

constexpr int B   = 2048;
constexpr int NA  = 60;
constexpr int DG  = 6;
constexpr int AF  = 37;
constexpr int BF  = 6;
constexpr int HID = 128;
constexpr int NC  = 12;
constexpr int BN  = B * NA;

// ---- scratch (allocation-free) ----
__device__ float    g_x1[BN * HID];
__device__ float    g_x2[BN * HID];
__device__ int      g_bidx[7 * BN];
__device__ int      g_bcnt[8];
// transposed weights, bf16 hi/lo packed as u32 (2 bf16/word):
// [deg][ch][ hi: KP2 words | lo: KP2 words ]
__device__ uint32_t g_WT1[6 * 128 * 48];    // KP2=24 (K=48)
__device__ uint32_t g_WT2[6 * 128 * 144];   // KP2=72 (K=144)
__device__ uint32_t g_WTo[128 * 144];       // KP2=72

__device__ __forceinline__ float htanh(float x) {
    float y; asm("tanh.approx.f32 %0, %1;" : "=f"(y) : "f"(x)); return y;
}
__device__ __forceinline__ uint16_t bf16b(float x) {
    return __bfloat16_as_ushort(__float2bfloat16(x));
}
// D(16x8,f32) += A(16x16,bf16 row) * B(16x8,bf16 col)
__device__ __forceinline__ void mma16816(float* d, const uint32_t* a, const uint32_t* b) {
    asm volatile("mma.sync.aligned.m16n8k16.row.col.f32.bf16.bf16.f32 "
                 "{%0,%1,%2,%3}, {%4,%5,%6,%7}, {%8,%9}, {%0,%1,%2,%3};"
                 : "+f"(d[0]), "+f"(d[1]), "+f"(d[2]), "+f"(d[3])
                 : "r"(a[0]), "r"(a[1]), "r"(a[2]), "r"(a[3]), "r"(b[0]), "r"(b[1]));
}

// ============================ prep ============================
__global__ void zero_cnt_kernel() { if (threadIdx.x < 8) g_bcnt[threadIdx.x] = 0; }

__global__ __launch_bounds__(256)
void prep_kernel(const int* __restrict__ edges) {
    int a = blockIdx.x * blockDim.x + threadIdx.x;
    if (a >= BN) return;
    int deg = 0;
    #pragma unroll
    for (int d = 0; d < DG; d++) deg += (edges[a * DG + d] >= 0);
    int pos = atomicAdd(&g_bcnt[deg], 1);
    g_bidx[deg * BN + pos] = a;
}

// transpose + hi/lo bf16 split: W[ndeg][IN][128] -> [deg][ch][hi KP2 | lo KP2]
__global__ __launch_bounds__(256)
void wprep_kernel(const float* __restrict__ W, int IN, int KP2, int ndeg, int which) {
    int idx = blockIdx.x * blockDim.x + threadIdx.x;
    if (idx >= ndeg * 128 * KP2) return;
    int p = idx % KP2;
    int ch = (idx / KP2) & 127;
    int deg = idx / (KP2 * 128);
    int k0 = 2 * p, k1 = 2 * p + 1;
    float w0 = (k0 < IN) ? W[(deg * IN + k0) * HID + ch] : 0.f;
    float w1 = (k1 < IN) ? W[(deg * IN + k1) * HID + ch] : 0.f;
    __nv_bfloat16 h0 = __float2bfloat16(w0), h1 = __float2bfloat16(w1);
    uint32_t hi = (uint32_t)__bfloat16_as_ushort(h0) | ((uint32_t)__bfloat16_as_ushort(h1) << 16);
    uint32_t lo = (uint32_t)bf16b(w0 - __bfloat162float(h0)) |
                  ((uint32_t)bf16b(w1 - __bfloat162float(h1)) << 16);
    uint32_t* row = (which == 0 ? g_WT1 : which == 1 ? g_WT2 : g_WTo) + (deg * 128 + ch) * (2 * KP2);
    row[p] = hi;
    row[KP2 + p] = lo;
}

// ============================ conv (mma.sync) ============================
// Tile: 64 atoms (M) x 128 ch (N), K = KUSED. A = feat bf16 hi/lo in SMEM
// (u32 words, row stride FS2); B = g_WT (global, L1-hot). 8 warps, each
// 4 m-tiles x 2 n-tiles, 3-term compensated bf16.
template <int INF, int KUSED, int FS2, int WSEL, bool USE_EXT>
__global__ __launch_bounds__(256)
void conv_mma_kernel(const float* __restrict__ Xext,
                     const float* __restrict__ bonds,
                     const int*   __restrict__ edges,
                     const float* __restrict__ bias) {
    constexpr int KP2 = KUSED / 2;
    constexpr int NCH = KUSED / 16;
    __shared__ uint32_t fh[64 * FS2];
    __shared__ uint32_t fl[64 * FS2];
    __shared__ int satom[64];

    const float* __restrict__ X = USE_EXT ? Xext : (const float*)g_x2;
    const uint32_t* __restrict__ WT = (WSEL == 0) ? g_WT1 : g_WT2;

    int deg = blockIdx.y;
    int cnt = g_bcnt[deg];
    int t0  = blockIdx.x * 64;
    if (t0 >= cnt) return;

    int tid = threadIdx.x, w = tid >> 5, lane = tid & 31;
    int tq = lane >> 2, tr = lane & 3;

    if (tid < 64) {
        int i = t0 + tid;
        satom[tid] = (i < cnt) ? g_bidx[deg * BN + i] : -1;
    }
    __syncthreads();

    if (deg >= DG) {      // degenerate bucket (empty in practice): zeros
        for (int idx = tid; idx < 64 * 32; idx += 256) {
            int al = idx >> 5, q = idx & 31;
            int a = satom[al];
            if (a >= 0)
                *reinterpret_cast<float4*>(&g_x1[(size_t)a * HID + q * 4]) =
                    make_float4(0.f, 0.f, 0.f, 0.f);
        }
        return;
    }

    // ---- stage A: warp w handles atoms w*8 .. w*8+7 ----
    for (int j = 0; j < 8; j++) {
        int al = w * 8 + j;
        int a  = satom[al];
        int aa = (a >= 0) ? a : 0;
        int e = -1;
        if (lane < DG && a >= 0) e = edges[aa * DG + lane];
        int nb[DG];
        #pragma unroll
        for (int d = 0; d < DG; d++) nb[d] = __shfl_sync(FULL, e, d);
        int rowbase = (aa / NA) * NA;
        const float* xr = X + (size_t)aa * INF;

        for (int kp = lane; kp < KP2; kp += 32) {
            float s[2];
            #pragma unroll
            for (int h = 0; h < 2; h++) {
                int k = 2 * kp + h;
                float v = 0.f;
                if (a >= 0) {
                    if (k < INF) {
                        v = xr[k];
                        #pragma unroll
                        for (int d = 0; d < DG; d++)
                            if (nb[d] >= 0) v += X[(size_t)(rowbase + nb[d]) * INF + k];
                    } else if (k < INF + BF) {
                        const float* bp = bonds + (size_t)aa * (DG * BF) + (k - INF);
                        v = bp[0] + bp[6] + bp[12] + bp[18] + bp[24] + bp[30];
                    }
                }
                s[h] = v;
            }
            __nv_bfloat16 h0 = __float2bfloat16(s[0]), h1 = __float2bfloat16(s[1]);
            uint32_t hi = (uint32_t)__bfloat16_as_ushort(h0) |
                          ((uint32_t)__bfloat16_as_ushort(h1) << 16);
            uint32_t lo = (uint32_t)bf16b(s[0] - __bfloat162float(h0)) |
                          ((uint32_t)bf16b(s[1] - __bfloat162float(h1)) << 16);
            fh[al * FS2 + kp] = hi;
            fl[al * FS2 + kp] = lo;
        }
    }
    __syncthreads();

    // ---- GEMM: warp w covers ch n0..n0+15 (2 n-tiles), all 64 atoms ----
    int n0 = w * 16;
    float acc[4][2][4];
    #pragma unroll
    for (int m = 0; m < 4; m++)
        #pragma unroll
        for (int j = 0; j < 2; j++)
            #pragma unroll
            for (int q = 0; q < 4; q++) acc[m][j][q] = 0.f;

    const uint32_t* wt0 = WT + (size_t)(deg * 128 + n0 + tq) * (2 * KP2);
    const uint32_t* wt1 = wt0 + (size_t)8 * (2 * KP2);

    #pragma unroll
    for (int c = 0; c < NCH; c++) {
        uint32_t Ah[4][4], Al[4][4];
        #pragma unroll
        for (int m = 0; m < 4; m++) {
            int r0 = (m * 16 + tq) * FS2 + c * 8 + tr;
            int r1 = r0 + 8 * FS2;
            Ah[m][0] = fh[r0];     Ah[m][1] = fh[r1];
            Ah[m][2] = fh[r0 + 4]; Ah[m][3] = fh[r1 + 4];
            Al[m][0] = fl[r0];     Al[m][1] = fl[r1];
            Al[m][2] = fl[r0 + 4]; Al[m][3] = fl[r1 + 4];
        }
        uint32_t Bh[2][2], Bl[2][2];
        Bh[0][0] = wt0[c * 8 + tr];       Bh[0][1] = wt0[c * 8 + tr + 4];
        Bl[0][0] = wt0[KP2 + c * 8 + tr]; Bl[0][1] = wt0[KP2 + c * 8 + tr + 4];
        Bh[1][0] = wt1[c * 8 + tr];       Bh[1][1] = wt1[c * 8 + tr + 4];
        Bl[1][0] = wt1[KP2 + c * 8 + tr]; Bl[1][1] = wt1[KP2 + c * 8 + tr + 4];

        #pragma unroll
        for (int m = 0; m < 4; m++)
            #pragma unroll
            for (int j = 0; j < 2; j++) {
                mma16816(acc[m][j], Ah[m], Bh[j]);
                mma16816(acc[m][j], Al[m], Bh[j]);
                mma16816(acc[m][j], Ah[m], Bl[j]);
            }
    }

    // ---- epilogue: bias + relu, direct float2 stores (row=atom, col=ch) ----
    float2 b2[2];
    #pragma unroll
    for (int j = 0; j < 2; j++) {
        int ch = n0 + j * 8 + 2 * tr;
        b2[j] = make_float2(bias[deg * HID + ch], bias[deg * HID + ch + 1]);
    }
    #pragma unroll
    for (int m = 0; m < 4; m++) {
        int a0 = satom[m * 16 + tq];
        int a1 = satom[m * 16 + tq + 8];
        #pragma unroll
        for (int j = 0; j < 2; j++) {
            int ch = n0 + j * 8 + 2 * tr;
            if (a0 >= 0)
                *reinterpret_cast<float2*>(&g_x1[(size_t)a0 * HID + ch]) =
                    make_float2(fmaxf(acc[m][j][0] + b2[j].x, 0.f),
                                fmaxf(acc[m][j][1] + b2[j].y, 0.f));
            if (a1 >= 0)
                *reinterpret_cast<float2*>(&g_x1[(size_t)a1 * HID + ch]) =
                    make_float2(fmaxf(acc[m][j][2] + b2[j].x, 0.f),
                                fmaxf(acc[m][j][3] + b2[j].y, 0.f));
        }
    }
}

// ============================ pool ============================
__global__ __launch_bounds__(256)
void pool_kernel(const int* __restrict__ edges) {
    int w = threadIdx.x >> 5, lane = threadIdx.x & 31;
    int a = blockIdx.x * 8 + w;
    int rowbase = (a / NA) * NA;
    int e = (lane < DG) ? edges[a * DG + lane] : -1;
    unsigned ball = __ballot_sync(FULL, e >= 0);
    int nb[DG];
    #pragma unroll
    for (int d = 0; d < DG; d++) nb[d] = __shfl_sync(FULL, e, d);
    int o = lane * 4;
    float4 v = *reinterpret_cast<const float4*>(g_x1 + (size_t)a * HID + o);
    #pragma unroll
    for (int d = 0; d < DG; d++) {
        if (nb[d] >= 0) {
            float4 u = *reinterpret_cast<const float4*>(g_x1 + (size_t)(rowbase + nb[d]) * HID + o);
            v.x = fmaxf(v.x, u.x); v.y = fmaxf(v.y, u.y);
            v.z = fmaxf(v.z, u.z); v.w = fmaxf(v.w, u.w);
        }
    }
    if (ball == 0u) v = make_float4(0.f, 0.f, 0.f, 0.f);
    *reinterpret_cast<float4*>(g_x2 + (size_t)a * HID + o) = v;
}

// ============================ gout (mma.sync) ============================
// Per graph: D[64 atoms x 128 ch] = pooled-feat x Wo; epilogue
// tanh+mask+sum over atoms (shfl butterfly) -> FC -> sigmoid.
__global__ __launch_bounds__(256)
void gout_mma_kernel(const int*   __restrict__ edges,
                     const float* __restrict__ bonds,
                     const float* __restrict__ bo,
                     const float* __restrict__ Wfc,
                     const float* __restrict__ bfc,
                     float* __restrict__ out) {
    constexpr int KUSED = 144, KP2 = 72, NCH = 9, FS2 = 73;
    __shared__ uint32_t fh[64 * FS2];
    __shared__ uint32_t fl[64 * FS2];
    __shared__ float svalid[64];
    __shared__ float sfp[HID];

    int tid = threadIdx.x, w = tid >> 5, lane = tid & 31;
    int tq = lane >> 2, tr = lane & 3;
    int g = blockIdx.x;
    int rowbase = g * NA;

    // ---- stage A: inline pool2 over g_x1 + bondsum + validity ----
    for (int j = 0; j < 8; j++) {
        int al = w * 8 + j;
        bool ok = (al < NA);
        int a = rowbase + (ok ? al : 0);
        int e = -1;
        if (lane < DG && ok) e = edges[a * DG + lane];
        unsigned ball = __ballot_sync(FULL, e >= 0);
        int nb[DG];
        #pragma unroll
        for (int d = 0; d < DG; d++) nb[d] = __shfl_sync(FULL, e, d);
        bool valid = ok && (ball != 0u);

        for (int kp = lane; kp < KP2; kp += 32) {
            float s[2];
            #pragma unroll
            for (int h = 0; h < 2; h++) {
                int k = 2 * kp + h;
                float v = 0.f;
                if (valid) {
                    if (k < HID) {
                        v = g_x1[(size_t)a * HID + k];
                        #pragma unroll
                        for (int d = 0; d < DG; d++)
                            if (nb[d] >= 0)
                                v = fmaxf(v, g_x1[(size_t)(rowbase + nb[d]) * HID + k]);
                    } else if (k < HID + BF) {
                        const float* bp = bonds + (size_t)a * (DG * BF) + (k - HID);
                        v = bp[0] + bp[6] + bp[12] + bp[18] + bp[24] + bp[30];
                    }
                }
                s[h] = v;
            }
            __nv_bfloat16 h0 = __float2bfloat16(s[0]), h1 = __float2bfloat16(s[1]);
            uint32_t hi = (uint32_t)__bfloat16_as_ushort(h0) |
                          ((uint32_t)__bfloat16_as_ushort(h1) << 16);
            uint32_t lo = (uint32_t)bf16b(s[0] - __bfloat162float(h0)) |
                          ((uint32_t)bf16b(s[1] - __bfloat162float(h1)) << 16);
            fh[al * FS2 + kp] = hi;
            fl[al * FS2 + kp] = lo;
        }
        if (lane == 0) svalid[al] = valid ? 1.f : 0.f;
    }
    __syncthreads();

    // ---- GEMM ----
    int n0 = w * 16;
    float acc[4][2][4];
    #pragma unroll
    for (int m = 0; m < 4; m++)
        #pragma unroll
        for (int j = 0; j < 2; j++)
            #pragma unroll
            for (int q = 0; q < 4; q++) acc[m][j][q] = 0.f;

    const uint32_t* wt0 = g_WTo + (size_t)(n0 + tq) * (2 * KP2);
    const uint32_t* wt1 = wt0 + (size_t)8 * (2 * KP2);

    #pragma unroll
    for (int c = 0; c < NCH; c++) {
        uint32_t Ah[4][4], Al[4][4];
        #pragma unroll
        for (int m = 0; m < 4; m++) {
            int r0 = (m * 16 + tq) * FS2 + c * 8 + tr;
            int r1 = r0 + 8 * FS2;
            Ah[m][0] = fh[r0];     Ah[m][1] = fh[r1];
            Ah[m][2] = fh[r0 + 4]; Ah[m][3] = fh[r1 + 4];
            Al[m][0] = fl[r0];     Al[m][1] = fl[r1];
            Al[m][2] = fl[r0 + 4]; Al[m][3] = fl[r1 + 4];
        }
        uint32_t Bh[2][2], Bl[2][2];
        Bh[0][0] = wt0[c * 8 + tr];       Bh[0][1] = wt0[c * 8 + tr + 4];
        Bl[0][0] = wt0[KP2 + c * 8 + tr]; Bl[0][1] = wt0[KP2 + c * 8 + tr + 4];
        Bh[1][0] = wt1[c * 8 + tr];       Bh[1][1] = wt1[c * 8 + tr + 4];
        Bl[1][0] = wt1[KP2 + c * 8 + tr]; Bl[1][1] = wt1[KP2 + c * 8 + tr + 4];

        #pragma unroll
        for (int m = 0; m < 4; m++)
            #pragma unroll
            for (int j = 0; j < 2; j++) {
                mma16816(acc[m][j], Ah[m], Bh[j]);
                mma16816(acc[m][j], Al[m], Bh[j]);
                mma16816(acc[m][j], Ah[m], Bl[j]);
            }
    }

    // ---- epilogue: bias + tanh + mask, reduce over atoms ----
    float2 b2[2];
    #pragma unroll
    for (int j = 0; j < 2; j++) {
        int ch = n0 + j * 8 + 2 * tr;
        b2[j] = make_float2(bo[ch], bo[ch + 1]);
    }
    float cs[2][2] = {{0.f, 0.f}, {0.f, 0.f}};
    #pragma unroll
    for (int m = 0; m < 4; m++) {
        float v0 = svalid[m * 16 + tq];
        float v1 = svalid[m * 16 + tq + 8];
        #pragma unroll
        for (int j = 0; j < 2; j++) {
            cs[j][0] += v0 * htanh(acc[m][j][0] + b2[j].x)
                      + v1 * htanh(acc[m][j][2] + b2[j].x);
            cs[j][1] += v0 * htanh(acc[m][j][1] + b2[j].y)
                      + v1 * htanh(acc[m][j][3] + b2[j].y);
        }
    }
    #pragma unroll
    for (int off = 4; off < 32; off <<= 1) {
        #pragma unroll
        for (int j = 0; j < 2; j++) {
            cs[j][0] += __shfl_xor_sync(FULL, cs[j][0], off);
            cs[j][1] += __shfl_xor_sync(FULL, cs[j][1], off);
        }
    }
    if (tq == 0) {
        #pragma unroll
        for (int j = 0; j < 2; j++) {
            int ch = n0 + j * 8 + 2 * tr;
            sfp[ch]     = cs[j][0];
            sfp[ch + 1] = cs[j][1];
        }
    }
    __syncthreads();

    // ---- FC + sigmoid ----
    if (tid < NC) {
        float v = bfc[tid];
        #pragma unroll 8
        for (int o = 0; o < HID; o++) v = fmaf(sfp[o], Wfc[o * NC + tid], v);
        out[g * NC + tid] = 1.0f / (1.0f + expf(-v));
    }
}

// ---------------------------------------------------------------------------
extern "C" void kernel_launch(void* const* d_in, const int* in_sizes, int n_in,
                              void* d_out, int out_size) {
    const float* atoms = (const float*)d_in[0];
    const float* bonds = (const float*)d_in[1];
    const int*   edges = (const int*)  d_in[2];
    const float* W1    = (const float*)d_in[3];
    const float* b1    = (const float*)d_in[4];
    const float* W2    = (const float*)d_in[5];
    const float* b2    = (const float*)d_in[6];
    const float* Wo    = (const float*)d_in[7];
    const float* bo    = (const float*)d_in[8];
    const float* Wfc   = (const float*)d_in[9];
    const float* bfc   = (const float*)d_in[10];
    float* out = (float*)d_out;

    // 0) bucket + weight transposes (hi/lo bf16)
    zero_cnt_kernel<<<1, 32>>>();
    prep_kernel<<<BN / 256, 256>>>(edges);
    wprep_kernel<<<(6 * 128 * 24 + 255) / 256, 256>>>(W1, 43, 24, 6, 0);
    wprep_kernel<<<(6 * 128 * 72 + 255) / 256, 256>>>(W2, 134, 72, 6, 1);
    wprep_kernel<<<(128 * 72 + 255) / 256, 256>>>(Wo, 134, 72, 1, 2);

    dim3 convGrid(BN / 64, 7);   // (1920, 7); inactive tiles exit on cnt check

    // 1) conv1: atoms -> g_x1   (K=48, FS2=25)
    conv_mma_kernel<AF, 48, 25, 0, true><<<convGrid, 256>>>(atoms, bonds, edges, b1);
    // 2) pool1: g_x1 -> g_x2
    pool_kernel<<<BN / 8, 256>>>(edges);
    // 3) conv2: g_x2 -> g_x1   (K=144, FS2=73)
    conv_mma_kernel<HID, 144, 73, 1, false><<<convGrid, 256>>>(nullptr, bonds, edges, b2);
    // 4) pool2 (inline) + gout + fc + sigmoid
    gout_mma_kernel<<<B, 256>>>(edges, bonds, bo, Wfc, bfc, out);
}

// round 10
// speedup vs baseline: 2.0638x; 1.0489x over previous
#include <cuda_runtime.h>
#include <cuda_bf16.h>
#include <cstdint>

#define FULL 0xFFFFFFFFu

constexpr int B   = 2048;
constexpr int NA  = 60;
constexpr int DG  = 6;
constexpr int AF  = 37;
constexpr int BF  = 6;
constexpr int HID = 128;
constexpr int NC  = 12;
constexpr int BN  = B * NA;
constexpr int MAXT = 1926;          // max total conv tiles: 122880/64 + 6

// ---- scratch (allocation-free) ----
__device__ float    g_x1[BN * HID];
__device__ float    g_x2[BN * HID];
__device__ int      g_bidx[7 * BN];
__device__ int      g_bcnt[8];
__device__ int      g_tbase[8];     // exclusive tile prefix per degree
// transposed weights, bf16 hi/lo packed as u32: [deg][ch][hi KP2 | lo KP2]
__device__ uint32_t g_WT1[6 * 128 * 48];
__device__ uint32_t g_WT2[6 * 128 * 144];
__device__ uint32_t g_WTo[128 * 144];

__device__ __forceinline__ float htanh(float x) {
    float y; asm("tanh.approx.f32 %0, %1;" : "=f"(y) : "f"(x)); return y;
}
__device__ __forceinline__ uint16_t bf16b(float x) {
    return __bfloat16_as_ushort(__float2bfloat16(x));
}
__device__ __forceinline__ uint32_t smem_u32(const void* p) {
    uint32_t a;
    asm("{ .reg .u64 t; cvta.to.shared.u64 t, %1; cvt.u32.u64 %0, t; }" : "=r"(a) : "l"(p));
    return a;
}
__device__ __forceinline__ void mma16816(float* d, const uint32_t* a, const uint32_t* b) {
    asm volatile("mma.sync.aligned.m16n8k16.row.col.f32.bf16.bf16.f32 "
                 "{%0,%1,%2,%3}, {%4,%5,%6,%7}, {%8,%9}, {%0,%1,%2,%3};"
                 : "+f"(d[0]), "+f"(d[1]), "+f"(d[2]), "+f"(d[3])
                 : "r"(a[0]), "r"(a[1]), "r"(a[2]), "r"(a[3]), "r"(b[0]), "r"(b[1]));
}
#define LDSM_X4(r, a) \
    asm volatile("ldmatrix.sync.aligned.m8n8.x4.shared.b16 {%0,%1,%2,%3}, [%4];" \
                 : "=r"((r)[0]), "=r"((r)[1]), "=r"((r)[2]), "=r"((r)[3]) : "r"(a))

// ============================ prep ============================
__global__ void zero_cnt_kernel() { if (threadIdx.x < 8) g_bcnt[threadIdx.x] = 0; }

__global__ __launch_bounds__(256)
void prep_kernel(const int* __restrict__ edges) {
    int a = blockIdx.x * blockDim.x + threadIdx.x;
    if (a >= BN) return;
    int deg = 0;
    #pragma unroll
    for (int d = 0; d < DG; d++) deg += (edges[a * DG + d] >= 0);
    int pos = atomicAdd(&g_bcnt[deg], 1);
    g_bidx[deg * BN + pos] = a;
}

__global__ void tileprep_kernel() {
    if (threadIdx.x == 0) {
        int s = 0;
        #pragma unroll
        for (int d = 0; d < 7; d++) { g_tbase[d] = s; s += (g_bcnt[d] + 63) >> 6; }
        g_tbase[7] = s;
    }
}

// fused transpose + hi/lo bf16 split for all three weight tensors
__device__ __forceinline__ void wsplit(const float* __restrict__ W, uint32_t* dst,
                                       int IN, int KP2, int sub) {
    int p = sub % KP2;
    int ch = (sub / KP2) & 127;
    int deg = sub / (KP2 * 128);
    int k0 = 2 * p, k1 = 2 * p + 1;
    float w0 = (k0 < IN) ? W[(deg * IN + k0) * HID + ch] : 0.f;
    float w1 = (k1 < IN) ? W[(deg * IN + k1) * HID + ch] : 0.f;
    __nv_bfloat16 h0 = __float2bfloat16(w0), h1 = __float2bfloat16(w1);
    uint32_t hi = (uint32_t)__bfloat16_as_ushort(h0) | ((uint32_t)__bfloat16_as_ushort(h1) << 16);
    uint32_t lo = (uint32_t)bf16b(w0 - __bfloat162float(h0)) |
                  ((uint32_t)bf16b(w1 - __bfloat162float(h1)) << 16);
    uint32_t* row = dst + (deg * 128 + ch) * (2 * KP2);
    row[p] = hi;
    row[KP2 + p] = lo;
}

__global__ __launch_bounds__(256)
void wprep_all_kernel(const float* __restrict__ W1, const float* __restrict__ W2,
                      const float* __restrict__ Wo) {
    constexpr int N1 = 6 * 128 * 24, N2 = 6 * 128 * 72, No = 128 * 72;
    int idx = blockIdx.x * blockDim.x + threadIdx.x;
    if (idx < N1)                wsplit(W1, g_WT1, 43, 24, idx);
    else if (idx < N1 + N2)      wsplit(W2, g_WT2, 134, 72, idx - N1);
    else if (idx < N1 + N2 + No) wsplit(Wo, g_WTo, 134, 72, idx - N1 - N2);
}

// ============================ conv (mma.sync) ============================
// Tile: 64 atoms x 128 ch, K=KUSED. A = feat bf16 hi/lo in SMEM (stride FS2
// words, 16B-aligned rows for ldmatrix); B = g_WT (L1-hot global).
// Compact 1-D grid via g_tbase. 3-term compensated bf16.
template <int INF, int KUSED, int FS2, int WSEL, bool USE_EXT>
__global__ __launch_bounds__(256)
void conv_mma_kernel(const float* __restrict__ Xext,
                     const float* __restrict__ bonds,
                     const int*   __restrict__ edges,
                     const float* __restrict__ bias) {
    constexpr int KP2 = KUSED / 2;
    constexpr int NCH = KUSED / 16;
    __shared__ __align__(16) uint32_t fh[64 * FS2];
    __shared__ __align__(16) uint32_t fl[64 * FS2];
    __shared__ int satom[64];

    const float* __restrict__ X = USE_EXT ? Xext : (const float*)g_x2;
    const uint32_t* __restrict__ WT = (WSEL == 0) ? g_WT1 : g_WT2;

    int bid = blockIdx.x;
    if (bid >= g_tbase[7]) return;
    int deg = 0;
    #pragma unroll
    for (int d = 0; d < 6; d++) if (bid >= g_tbase[d + 1]) deg = d + 1;
    int cnt = g_bcnt[deg];
    int t0  = (bid - g_tbase[deg]) * 64;

    int tid = threadIdx.x, w = tid >> 5, lane = tid & 31;
    int tq = lane >> 2, tr = lane & 3;

    if (tid < 64) {
        int i = t0 + tid;
        satom[tid] = (i < cnt) ? g_bidx[deg * BN + i] : -1;
    }
    __syncthreads();

    if (deg >= DG) {      // deg==6 bucket (empty in practice): zero outputs
        for (int idx = tid; idx < 64 * 32; idx += 256) {
            int al = idx >> 5, q = idx & 31;
            int a = satom[al];
            if (a >= 0)
                *reinterpret_cast<float4*>(&g_x1[(size_t)a * HID + q * 4]) =
                    make_float4(0.f, 0.f, 0.f, 0.f);
        }
        return;
    }

    // ---- stage A: warp w handles atoms w*8 .. w*8+7 ----
    for (int j = 0; j < 8; j++) {
        int al = w * 8 + j;
        int a  = satom[al];
        int aa = (a >= 0) ? a : 0;
        int e = -1;
        if (lane < DG && a >= 0) e = edges[aa * DG + lane];
        int nb[DG];
        #pragma unroll
        for (int d = 0; d < DG; d++) nb[d] = __shfl_sync(FULL, e, d);
        int rowbase = (aa / NA) * NA;
        const float* xr = X + (size_t)aa * INF;

        for (int kp = lane; kp < KP2; kp += 32) {
            float s0 = 0.f, s1 = 0.f;
            if (a >= 0) {
                if ((INF % 2 == 0) && (2 * kp + 1 < INF)) {
                    // fast path: paired float2 gather
                    float2 v = *reinterpret_cast<const float2*>(xr + 2 * kp);
                    s0 = v.x; s1 = v.y;
                    #pragma unroll
                    for (int d = 0; d < DG; d++)
                        if (nb[d] >= 0) {
                            float2 u = *reinterpret_cast<const float2*>(
                                X + (size_t)(rowbase + nb[d]) * INF + 2 * kp);
                            s0 += u.x; s1 += u.y;
                        }
                } else {
                    #pragma unroll
                    for (int h = 0; h < 2; h++) {
                        int k = 2 * kp + h;
                        float v = 0.f;
                        if (k < INF) {
                            v = xr[k];
                            #pragma unroll
                            for (int d = 0; d < DG; d++)
                                if (nb[d] >= 0) v += X[(size_t)(rowbase + nb[d]) * INF + k];
                        } else if (k < INF + BF) {
                            const float* bp = bonds + (size_t)aa * (DG * BF) + (k - INF);
                            v = bp[0] + bp[6] + bp[12] + bp[18] + bp[24] + bp[30];
                        }
                        if (h == 0) s0 = v; else s1 = v;
                    }
                }
            }
            __nv_bfloat16 h0 = __float2bfloat16(s0), h1 = __float2bfloat16(s1);
            uint32_t hi = (uint32_t)__bfloat16_as_ushort(h0) |
                          ((uint32_t)__bfloat16_as_ushort(h1) << 16);
            uint32_t lo = (uint32_t)bf16b(s0 - __bfloat162float(h0)) |
                          ((uint32_t)bf16b(s1 - __bfloat162float(h1)) << 16);
            fh[al * FS2 + kp] = hi;
            fl[al * FS2 + kp] = lo;
        }
    }
    __syncthreads();

    // ---- GEMM: warp w -> ch n0..n0+15, all 64 atoms; A via ldmatrix ----
    int n0 = w * 16;
    float acc[4][2][4];
    #pragma unroll
    for (int m = 0; m < 4; m++)
        #pragma unroll
        for (int j = 0; j < 2; j++)
            #pragma unroll
            for (int q = 0; q < 4; q++) acc[m][j][q] = 0.f;

    const uint32_t* wt0 = WT + (size_t)(deg * 128 + n0 + tq) * (2 * KP2);
    const uint32_t* wt1 = wt0 + (size_t)8 * (2 * KP2);

    uint32_t ah_base = smem_u32(fh) + 4 * ((lane & 15) * FS2 + (lane >> 4) * 4);
    uint32_t al_base = smem_u32(fl) + 4 * ((lane & 15) * FS2 + (lane >> 4) * 4);

    #pragma unroll
    for (int c = 0; c < NCH; c++) {
        uint32_t Ah[4][4], Al[4][4];
        #pragma unroll
        for (int m = 0; m < 4; m++) {
            uint32_t off = 4 * (m * 16 * FS2 + c * 8);
            LDSM_X4(Ah[m], ah_base + off);
            LDSM_X4(Al[m], al_base + off);
        }
        uint32_t Bh[2][2], Bl[2][2];
        Bh[0][0] = wt0[c * 8 + tr];       Bh[0][1] = wt0[c * 8 + tr + 4];
        Bl[0][0] = wt0[KP2 + c * 8 + tr]; Bl[0][1] = wt0[KP2 + c * 8 + tr + 4];
        Bh[1][0] = wt1[c * 8 + tr];       Bh[1][1] = wt1[c * 8 + tr + 4];
        Bl[1][0] = wt1[KP2 + c * 8 + tr]; Bl[1][1] = wt1[KP2 + c * 8 + tr + 4];

        #pragma unroll
        for (int m = 0; m < 4; m++)
            #pragma unroll
            for (int j = 0; j < 2; j++) {
                mma16816(acc[m][j], Ah[m], Bh[j]);
                mma16816(acc[m][j], Al[m], Bh[j]);
                mma16816(acc[m][j], Ah[m], Bl[j]);
            }
    }

    // ---- epilogue: bias + relu, direct float2 stores ----
    float2 b2[2];
    #pragma unroll
    for (int j = 0; j < 2; j++) {
        int ch = n0 + j * 8 + 2 * tr;
        b2[j] = make_float2(bias[deg * HID + ch], bias[deg * HID + ch + 1]);
    }
    #pragma unroll
    for (int m = 0; m < 4; m++) {
        int a0 = satom[m * 16 + tq];
        int a1 = satom[m * 16 + tq + 8];
        #pragma unroll
        for (int j = 0; j < 2; j++) {
            int ch = n0 + j * 8 + 2 * tr;
            if (a0 >= 0)
                *reinterpret_cast<float2*>(&g_x1[(size_t)a0 * HID + ch]) =
                    make_float2(fmaxf(acc[m][j][0] + b2[j].x, 0.f),
                                fmaxf(acc[m][j][1] + b2[j].y, 0.f));
            if (a1 >= 0)
                *reinterpret_cast<float2*>(&g_x1[(size_t)a1 * HID + ch]) =
                    make_float2(fmaxf(acc[m][j][2] + b2[j].x, 0.f),
                                fmaxf(acc[m][j][3] + b2[j].y, 0.f));
        }
    }
}

// ============================ pool ============================
__global__ __launch_bounds__(256)
void pool_kernel(const int* __restrict__ edges) {
    int w = threadIdx.x >> 5, lane = threadIdx.x & 31;
    int a = blockIdx.x * 8 + w;
    int rowbase = (a / NA) * NA;
    int e = (lane < DG) ? edges[a * DG + lane] : -1;
    unsigned ball = __ballot_sync(FULL, e >= 0);
    int nb[DG];
    #pragma unroll
    for (int d = 0; d < DG; d++) nb[d] = __shfl_sync(FULL, e, d);
    int o = lane * 4;
    float4 v = *reinterpret_cast<const float4*>(g_x1 + (size_t)a * HID + o);
    #pragma unroll
    for (int d = 0; d < DG; d++) {
        if (nb[d] >= 0) {
            float4 u = *reinterpret_cast<const float4*>(g_x1 + (size_t)(rowbase + nb[d]) * HID + o);
            v.x = fmaxf(v.x, u.x); v.y = fmaxf(v.y, u.y);
            v.z = fmaxf(v.z, u.z); v.w = fmaxf(v.w, u.w);
        }
    }
    if (ball == 0u) v = make_float4(0.f, 0.f, 0.f, 0.f);
    *reinterpret_cast<float4*>(g_x2 + (size_t)a * HID + o) = v;
}

// ============================ gout (mma.sync) ============================
__global__ __launch_bounds__(256)
void gout_mma_kernel(const int*   __restrict__ edges,
                     const float* __restrict__ bonds,
                     const float* __restrict__ bo,
                     const float* __restrict__ Wfc,
                     const float* __restrict__ bfc,
                     float* __restrict__ out) {
    constexpr int KP2 = 72, NCH = 9, FS2 = 76;
    __shared__ __align__(16) uint32_t fh[64 * FS2];
    __shared__ __align__(16) uint32_t fl[64 * FS2];
    __shared__ float svalid[64];
    __shared__ float sfp[HID];

    int tid = threadIdx.x, w = tid >> 5, lane = tid & 31;
    int tq = lane >> 2, tr = lane & 3;
    int g = blockIdx.x;
    int rowbase = g * NA;

    // ---- stage A: inline pool2 (float2 fast path) + bondsum + validity ----
    for (int j = 0; j < 8; j++) {
        int al = w * 8 + j;
        bool ok = (al < NA);
        int a = rowbase + (ok ? al : 0);
        int e = -1;
        if (lane < DG && ok) e = edges[a * DG + lane];
        unsigned ball = __ballot_sync(FULL, e >= 0);
        int nb[DG];
        #pragma unroll
        for (int d = 0; d < DG; d++) nb[d] = __shfl_sync(FULL, e, d);
        bool valid = ok && (ball != 0u);

        for (int kp = lane; kp < KP2; kp += 32) {
            float s0 = 0.f, s1 = 0.f;
            if (valid) {
                if (2 * kp + 1 < HID) {
                    float2 v = *reinterpret_cast<const float2*>(g_x1 + (size_t)a * HID + 2 * kp);
                    #pragma unroll
                    for (int d = 0; d < DG; d++)
                        if (nb[d] >= 0) {
                            float2 u = *reinterpret_cast<const float2*>(
                                g_x1 + (size_t)(rowbase + nb[d]) * HID + 2 * kp);
                            v.x = fmaxf(v.x, u.x); v.y = fmaxf(v.y, u.y);
                        }
                    s0 = v.x; s1 = v.y;
                } else {
                    #pragma unroll
                    for (int h = 0; h < 2; h++) {
                        int k = 2 * kp + h;
                        float v = 0.f;
                        if (k < HID + BF && k >= HID) {
                            const float* bp = bonds + (size_t)a * (DG * BF) + (k - HID);
                            v = bp[0] + bp[6] + bp[12] + bp[18] + bp[24] + bp[30];
                        }
                        if (h == 0) s0 = v; else s1 = v;
                    }
                }
            }
            __nv_bfloat16 h0 = __float2bfloat16(s0), h1 = __float2bfloat16(s1);
            uint32_t hi = (uint32_t)__bfloat16_as_ushort(h0) |
                          ((uint32_t)__bfloat16_as_ushort(h1) << 16);
            uint32_t lo = (uint32_t)bf16b(s0 - __bfloat162float(h0)) |
                          ((uint32_t)bf16b(s1 - __bfloat162float(h1)) << 16);
            fh[al * FS2 + kp] = hi;
            fl[al * FS2 + kp] = lo;
        }
        if (lane == 0) svalid[al] = valid ? 1.f : 0.f;
    }
    __syncthreads();

    // ---- GEMM ----
    int n0 = w * 16;
    float acc[4][2][4];
    #pragma unroll
    for (int m = 0; m < 4; m++)
        #pragma unroll
        for (int j = 0; j < 2; j++)
            #pragma unroll
            for (int q = 0; q < 4; q++) acc[m][j][q] = 0.f;

    const uint32_t* wt0 = g_WTo + (size_t)(n0 + tq) * (2 * KP2);
    const uint32_t* wt1 = wt0 + (size_t)8 * (2 * KP2);

    uint32_t ah_base = smem_u32(fh) + 4 * ((lane & 15) * FS2 + (lane >> 4) * 4);
    uint32_t al_base = smem_u32(fl) + 4 * ((lane & 15) * FS2 + (lane >> 4) * 4);

    #pragma unroll
    for (int c = 0; c < NCH; c++) {
        uint32_t Ah[4][4], Al[4][4];
        #pragma unroll
        for (int m = 0; m < 4; m++) {
            uint32_t off = 4 * (m * 16 * FS2 + c * 8);
            LDSM_X4(Ah[m], ah_base + off);
            LDSM_X4(Al[m], al_base + off);
        }
        uint32_t Bh[2][2], Bl[2][2];
        Bh[0][0] = wt0[c * 8 + tr];       Bh[0][1] = wt0[c * 8 + tr + 4];
        Bl[0][0] = wt0[KP2 + c * 8 + tr]; Bl[0][1] = wt0[KP2 + c * 8 + tr + 4];
        Bh[1][0] = wt1[c * 8 + tr];       Bh[1][1] = wt1[c * 8 + tr + 4];
        Bl[1][0] = wt1[KP2 + c * 8 + tr]; Bl[1][1] = wt1[KP2 + c * 8 + tr + 4];

        #pragma unroll
        for (int m = 0; m < 4; m++)
            #pragma unroll
            for (int j = 0; j < 2; j++) {
                mma16816(acc[m][j], Ah[m], Bh[j]);
                mma16816(acc[m][j], Al[m], Bh[j]);
                mma16816(acc[m][j], Ah[m], Bl[j]);
            }
    }

    // ---- epilogue: bias + tanh + mask, reduce over atoms ----
    float2 b2[2];
    #pragma unroll
    for (int j = 0; j < 2; j++) {
        int ch = n0 + j * 8 + 2 * tr;
        b2[j] = make_float2(bo[ch], bo[ch + 1]);
    }
    float cs[2][2] = {{0.f, 0.f}, {0.f, 0.f}};
    #pragma unroll
    for (int m = 0; m < 4; m++) {
        float v0 = svalid[m * 16 + tq];
        float v1 = svalid[m * 16 + tq + 8];
        #pragma unroll
        for (int j = 0; j < 2; j++) {
            cs[j][0] += v0 * htanh(acc[m][j][0] + b2[j].x)
                      + v1 * htanh(acc[m][j][2] + b2[j].x);
            cs[j][1] += v0 * htanh(acc[m][j][1] + b2[j].y)
                      + v1 * htanh(acc[m][j][3] + b2[j].y);
        }
    }
    #pragma unroll
    for (int off = 4; off < 32; off <<= 1) {
        #pragma unroll
        for (int j = 0; j < 2; j++) {
            cs[j][0] += __shfl_xor_sync(FULL, cs[j][0], off);
            cs[j][1] += __shfl_xor_sync(FULL, cs[j][1], off);
        }
    }
    if (tq == 0) {
        #pragma unroll
        for (int j = 0; j < 2; j++) {
            int ch = n0 + j * 8 + 2 * tr;
            sfp[ch]     = cs[j][0];
            sfp[ch + 1] = cs[j][1];
        }
    }
    __syncthreads();

    if (tid < NC) {
        float v = bfc[tid];
        #pragma unroll 8
        for (int o = 0; o < HID; o++) v = fmaf(sfp[o], Wfc[o * NC + tid], v);
        out[g * NC + tid] = 1.0f / (1.0f + expf(-v));
    }
}

// ---------------------------------------------------------------------------
extern "C" void kernel_launch(void* const* d_in, const int* in_sizes, int n_in,
                              void* d_out, int out_size) {
    const float* atoms = (const float*)d_in[0];
    const float* bonds = (const float*)d_in[1];
    const int*   edges = (const int*)  d_in[2];
    const float* W1    = (const float*)d_in[3];
    const float* b1    = (const float*)d_in[4];
    const float* W2    = (const float*)d_in[5];
    const float* b2    = (const float*)d_in[6];
    const float* Wo    = (const float*)d_in[7];
    const float* bo    = (const float*)d_in[8];
    const float* Wfc   = (const float*)d_in[9];
    const float* bfc   = (const float*)d_in[10];
    float* out = (float*)d_out;

    zero_cnt_kernel<<<1, 32>>>();
    prep_kernel<<<BN / 256, 256>>>(edges);
    tileprep_kernel<<<1, 32>>>();
    wprep_all_kernel<<<(6*128*24 + 6*128*72 + 128*72 + 255) / 256, 256>>>(W1, W2, Wo);

    // conv1: K=48, FS2=28 ; conv2: K=144, FS2=76  (16B-aligned rows for ldmatrix)
    conv_mma_kernel<AF, 48, 28, 0, true><<<MAXT, 256>>>(atoms, bonds, edges, b1);
    pool_kernel<<<BN / 8, 256>>>(edges);
    conv_mma_kernel<HID, 144, 76, 1, false><<<MAXT, 256>>>(nullptr, bonds, edges, b2);
    gout_mma_kernel<<<B, 256>>>(edges, bonds, bo, Wfc, bfc, out);
}